// round 4
// baseline (speedup 1.0000x reference)
#include <cuda_runtime.h>
#include <cuda_fp16.h>
#include <math.h>

#define NN 100000
#define EE 1600000
#define FH 64      // input/hidden width
#define CC 40      // output classes
#define P3S 48     // padded layer-3 P row stride in halves (96 B = 3 sectors)

// ---------------- scratch (device globals; no allocation allowed) ----------
__device__ int   g_deg_out[NN];
__device__ int   g_deg_in[NN];
__device__ float g_invo[NN];
__device__ float g_invi[NN];
__device__ int   g_start[NN];              // CSR row start
__device__ int   g_pos[NN];                // bump cursor per row
__device__ uint2 g_csr[EE];                // .x = col, .y = weight bits
__device__ unsigned int g_ctr;             // global bump counter
__device__ __half2 g_p[(size_t)NN * (FH / 2)];  // fp16 GEMM output (gathered)
__device__ float g_y[(size_t)NN * FH];     // SpMM output layer 1

// ---------------- f32x2 packed-FMA helpers (Blackwell FFMA2) ----------------
__device__ __forceinline__ unsigned long long pack2f(float lo, float hi) {
    unsigned long long r;
    asm("mov.b64 %0, {%1, %2};" : "=l"(r) : "f"(lo), "f"(hi));
    return r;
}
__device__ __forceinline__ void fma2f(unsigned long long& d,
                                      unsigned long long a, unsigned long long b) {
    asm("fma.rn.f32x2 %0, %1, %2, %0;" : "+l"(d) : "l"(a), "l"(b));
}
__device__ __forceinline__ float2 unpack2f(unsigned long long v) {
    float lo, hi;
    asm("mov.b64 {%0, %1}, %2;" : "=f"(lo), "=f"(hi) : "l"(v));
    return make_float2(lo, hi);
}

// ---------------- zero -------------------------------------------------------
__global__ void zero_kernel() {
    int i = blockIdx.x * blockDim.x + threadIdx.x;
    if (i < NN) { g_deg_out[i] = 0; g_deg_in[i] = 0; }
    if (i == 0) g_ctr = 0u;
}

// ---------------- degree histogram ------------------------------------------
__global__ void hist_kernel(const int* __restrict__ row, const int* __restrict__ col) {
    int e = blockIdx.x * blockDim.x + threadIdx.x;
    if (e < EE) {
        atomicAdd(&g_deg_out[row[e]], 1);
        atomicAdd(&g_deg_in[col[e]], 1);
    }
}

// ---------------- range assignment (warp-aggregated bump alloc) + inv degs --
__global__ void ranges_kernel() {
    int i = blockIdx.x * blockDim.x + threadIdx.x;
    int lane = threadIdx.x & 31;
    int d = (i < NN) ? g_deg_out[i] : 0;
    int incl = d;
#pragma unroll
    for (int o = 1; o < 32; o <<= 1) {
        int v = __shfl_up_sync(0xffffffffu, incl, o);
        if (lane >= o) incl += v;
    }
    int total = __shfl_sync(0xffffffffu, incl, 31);
    unsigned int base = 0;
    if (lane == 31) base = atomicAdd(&g_ctr, (unsigned int)total);
    base = __shfl_sync(0xffffffffu, base, 31);
    if (i < NN) {
        int st = (int)base + (incl - d);
        g_start[i] = st;
        g_pos[i]   = st;
        int di = g_deg_in[i];
        g_invo[i] = (d  > 0) ? rsqrtf((float)d)  : 0.f;
        g_invi[i] = (di > 0) ? rsqrtf((float)di) : 0.f;
    }
}

// ---------------- edge scatter into CSR --------------------------------------
__global__ void scatter_kernel(const int* __restrict__ row, const int* __restrict__ col) {
    int e = blockIdx.x * blockDim.x + threadIdx.x;
    if (e >= EE) return;
    int r = row[e], c = col[e];
    int p = atomicAdd(&g_pos[r], 1);
    float w = g_invo[r] * g_invi[c];
    g_csr[p] = make_uint2((unsigned int)c, __float_as_uint(w));
}

// ---------------- dense GEMM: P[N,OUT](fp16) = (relu?)X[N,64] @ W[64,OUT] ----
// f32x2 packed FMA: 32 FFMA2 per output instead of 64 FFMA.
template <int OUT, int PSTRIDE, int YD, int TILES, bool RELU>
__global__ void gemm_kernel(const float* __restrict__ X,
                            const float* __restrict__ W,
                            __half* __restrict__ P) {
    __shared__ float sX[YD][FH];
    const int tx = threadIdx.x;            // 0..OUT-1
    const int ty = threadIdx.y;            // 0..YD-1
    const int tid = ty * OUT + tx;
    const int nthreads = OUT * YD;

    unsigned long long wp[FH / 2];
#pragma unroll
    for (int k2 = 0; k2 < FH / 2; k2++)
        wp[k2] = pack2f(W[(2 * k2) * OUT + tx], W[(2 * k2 + 1) * OUT + tx]);

    const int base = blockIdx.x * (YD * TILES);
#pragma unroll 1
    for (int t = 0; t < TILES; t++) {
        const int nb = base + t * YD;
        for (int idx = tid; idx < YD * FH; idx += nthreads) {
            int r = idx >> 6, c = idx & 63;
            int n = nb + r;
            float v = (n < NN) ? X[(size_t)n * FH + c] : 0.f;
            if (RELU) v = fmaxf(v, 0.f);
            sX[r][c] = v;
        }
        __syncthreads();
        const int n = nb + ty;
        if (n < NN) {
            const unsigned long long* sxd =
                reinterpret_cast<const unsigned long long*>(&sX[ty][0]);
            unsigned long long acc0 = pack2f(0.f, 0.f);
            unsigned long long acc1 = pack2f(0.f, 0.f);
#pragma unroll
            for (int k2 = 0; k2 < FH / 2; k2 += 2) {
                fma2f(acc0, sxd[k2],     wp[k2]);
                fma2f(acc1, sxd[k2 + 1], wp[k2 + 1]);
            }
            float2 r0 = unpack2f(acc0);
            float2 r1 = unpack2f(acc1);
            P[(size_t)n * PSTRIDE + tx] = __float2half((r0.x + r0.y) + (r1.x + r1.y));
        }
        __syncthreads();
    }
}

// ---------------- gather SpMM, width 64 (fp16 rows): one warp per node -------
__global__ void spmm64_kernel(const __half2* __restrict__ P,
                              const float* __restrict__ bias,
                              float* __restrict__ Y) {
    int n = (blockIdx.x * blockDim.x + threadIdx.x) >> 5;
    int lane = threadIdx.x & 31;
    if (n >= NN) return;
    int s = g_start[n];
    int d = g_deg_out[n];
    float a0 = bias[2 * lane], a1 = bias[2 * lane + 1];
    const uint2* cw = g_csr + s;
    int e = 0;
    for (; e + 8 <= d; e += 8) {
        uint2 p0 = cw[e],     p1 = cw[e + 1], p2 = cw[e + 2], p3 = cw[e + 3];
        uint2 p4 = cw[e + 4], p5 = cw[e + 5], p6 = cw[e + 6], p7 = cw[e + 7];
        float2 v0 = __half22float2(__ldg(P + (size_t)p0.x * (FH / 2) + lane));
        float2 v1 = __half22float2(__ldg(P + (size_t)p1.x * (FH / 2) + lane));
        float2 v2 = __half22float2(__ldg(P + (size_t)p2.x * (FH / 2) + lane));
        float2 v3 = __half22float2(__ldg(P + (size_t)p3.x * (FH / 2) + lane));
        float2 v4 = __half22float2(__ldg(P + (size_t)p4.x * (FH / 2) + lane));
        float2 v5 = __half22float2(__ldg(P + (size_t)p5.x * (FH / 2) + lane));
        float2 v6 = __half22float2(__ldg(P + (size_t)p6.x * (FH / 2) + lane));
        float2 v7 = __half22float2(__ldg(P + (size_t)p7.x * (FH / 2) + lane));
        float w0 = __uint_as_float(p0.y), w1 = __uint_as_float(p1.y);
        float w2 = __uint_as_float(p2.y), w3 = __uint_as_float(p3.y);
        float w4 = __uint_as_float(p4.y), w5 = __uint_as_float(p5.y);
        float w6 = __uint_as_float(p6.y), w7 = __uint_as_float(p7.y);
        a0 = fmaf(w0, v0.x, a0); a1 = fmaf(w0, v0.y, a1);
        a0 = fmaf(w1, v1.x, a0); a1 = fmaf(w1, v1.y, a1);
        a0 = fmaf(w2, v2.x, a0); a1 = fmaf(w2, v2.y, a1);
        a0 = fmaf(w3, v3.x, a0); a1 = fmaf(w3, v3.y, a1);
        a0 = fmaf(w4, v4.x, a0); a1 = fmaf(w4, v4.y, a1);
        a0 = fmaf(w5, v5.x, a0); a1 = fmaf(w5, v5.y, a1);
        a0 = fmaf(w6, v6.x, a0); a1 = fmaf(w6, v6.y, a1);
        a0 = fmaf(w7, v7.x, a0); a1 = fmaf(w7, v7.y, a1);
    }
    if (e + 4 <= d) {
        uint2 p0 = cw[e], p1 = cw[e + 1], p2 = cw[e + 2], p3 = cw[e + 3];
        float2 v0 = __half22float2(__ldg(P + (size_t)p0.x * (FH / 2) + lane));
        float2 v1 = __half22float2(__ldg(P + (size_t)p1.x * (FH / 2) + lane));
        float2 v2 = __half22float2(__ldg(P + (size_t)p2.x * (FH / 2) + lane));
        float2 v3 = __half22float2(__ldg(P + (size_t)p3.x * (FH / 2) + lane));
        float w0 = __uint_as_float(p0.y), w1 = __uint_as_float(p1.y);
        float w2 = __uint_as_float(p2.y), w3 = __uint_as_float(p3.y);
        a0 = fmaf(w0, v0.x, a0); a1 = fmaf(w0, v0.y, a1);
        a0 = fmaf(w1, v1.x, a0); a1 = fmaf(w1, v1.y, a1);
        a0 = fmaf(w2, v2.x, a0); a1 = fmaf(w2, v2.y, a1);
        a0 = fmaf(w3, v3.x, a0); a1 = fmaf(w3, v3.y, a1);
        e += 4;
    }
    for (; e < d; e++) {
        uint2 p0 = cw[e];
        float2 v0 = __half22float2(__ldg(P + (size_t)p0.x * (FH / 2) + lane));
        float w0 = __uint_as_float(p0.y);
        a0 = fmaf(w0, v0.x, a0); a1 = fmaf(w0, v0.y, a1);
    }
    *reinterpret_cast<float2*>(Y + (size_t)n * FH + 2 * lane) = make_float2(a0, a1);
}

// ---------------- gather SpMM width 40 (padded fp16 rows) + log-softmax ------
__global__ void spmm40_lsm_kernel(const __half2* __restrict__ P,
                                  const float* __restrict__ bias,
                                  float* __restrict__ O) {
    int n = (blockIdx.x * blockDim.x + threadIdx.x) >> 5;
    int lane = threadIdx.x & 31;
    if (n >= NN) return;
    int s = g_start[n];
    int d = g_deg_out[n];
    const bool act = (lane < CC / 2);   // lanes 0..19 own feature pairs
    float a0 = act ? bias[2 * lane] : 0.f;
    float a1 = act ? bias[2 * lane + 1] : 0.f;
    const uint2* cw = g_csr + s;
    int e = 0;
    for (; e + 4 <= d; e += 4) {
        uint2 p0 = cw[e], p1 = cw[e + 1], p2 = cw[e + 2], p3 = cw[e + 3];
        float2 v0 = act ? __half22float2(__ldg(P + (size_t)p0.x * (P3S / 2) + lane))
                        : make_float2(0.f, 0.f);
        float2 v1 = act ? __half22float2(__ldg(P + (size_t)p1.x * (P3S / 2) + lane))
                        : make_float2(0.f, 0.f);
        float2 v2 = act ? __half22float2(__ldg(P + (size_t)p2.x * (P3S / 2) + lane))
                        : make_float2(0.f, 0.f);
        float2 v3 = act ? __half22float2(__ldg(P + (size_t)p3.x * (P3S / 2) + lane))
                        : make_float2(0.f, 0.f);
        float w0 = __uint_as_float(p0.y), w1 = __uint_as_float(p1.y);
        float w2 = __uint_as_float(p2.y), w3 = __uint_as_float(p3.y);
        a0 = fmaf(w0, v0.x, a0); a1 = fmaf(w0, v0.y, a1);
        a0 = fmaf(w1, v1.x, a0); a1 = fmaf(w1, v1.y, a1);
        a0 = fmaf(w2, v2.x, a0); a1 = fmaf(w2, v2.y, a1);
        a0 = fmaf(w3, v3.x, a0); a1 = fmaf(w3, v3.y, a1);
    }
    for (; e < d; e++) {
        uint2 p0 = cw[e];
        if (act) {
            float2 v0 = __half22float2(__ldg(P + (size_t)p0.x * (P3S / 2) + lane));
            float w0 = __uint_as_float(p0.y);
            a0 = fmaf(w0, v0.x, a0); a1 = fmaf(w0, v0.y, a1);
        }
    }
    // fused log-softmax over 40 values
    float m = act ? fmaxf(a0, a1) : -INFINITY;
#pragma unroll
    for (int o = 16; o; o >>= 1) m = fmaxf(m, __shfl_xor_sync(0xffffffffu, m, o));
    float sum = act ? (expf(a0 - m) + expf(a1 - m)) : 0.f;
#pragma unroll
    for (int o = 16; o; o >>= 1) sum += __shfl_xor_sync(0xffffffffu, sum, o);
    float ls = m + logf(sum);
    if (act) {
        *reinterpret_cast<float2*>(O + (size_t)n * CC + 2 * lane) =
            make_float2(a0 - ls, a1 - ls);
    }
}

// ---------------- launch -----------------------------------------------------
extern "C" void kernel_launch(void* const* d_in, const int* in_sizes, int n_in,
                              void* d_out, int out_size) {
    const float* x   = (const float*)d_in[0];
    const int*   ei  = (const int*)d_in[1];
    const int*   rowp = ei;
    const int*   colp = ei + EE;
    const float* W1s = (const float*)d_in[2];
    const float* b1s = (const float*)d_in[3];
    const float* W2s = (const float*)d_in[6];
    const float* b2s = (const float*)d_in[7];
    const float* Wos = (const float*)d_in[10];
    const float* bos = (const float*)d_in[11];

    float* out = (float*)d_out;
    float* h   = out;                       // [N, 64]
    float* lsm = out + (size_t)NN * FH;     // [N, 40]

    __half2* pp;
    float* py;
    cudaGetSymbolAddress((void**)&pp, g_p);
    cudaGetSymbolAddress((void**)&py, g_y);

    const int T = 256;

    // ---- CSR build (recomputed every call — determinism rule) ----
    zero_kernel<<<(NN + T - 1) / T, T>>>();
    hist_kernel<<<(EE + T - 1) / T, T>>>(rowp, colp);
    ranges_kernel<<<(NN + T - 1) / T, T>>>();
    scatter_kernel<<<(EE + T - 1) / T, T>>>(rowp, colp);

    const int WARPS_GRID = (NN * 32 + T - 1) / T;

    // ---- layer 1: x0 = A @ (x @ W1s) + b1s ----
    {
        const int NPB = 4 * 16;
        gemm_kernel<FH, FH, 4, 16, false><<<(NN + NPB - 1) / NPB, dim3(FH, 4)>>>(x, W1s, (__half*)pp);
        spmm64_kernel<<<WARPS_GRID, T>>>(pp, b1s, py);
    }
    // ---- layer 2: h = A @ (relu(x0) @ W2s) + b2s  (h -> d_out) ----
    {
        const int NPB = 4 * 16;
        gemm_kernel<FH, FH, 4, 16, true><<<(NN + NPB - 1) / NPB, dim3(FH, 4)>>>(py, W2s, (__half*)pp);
        spmm64_kernel<<<WARPS_GRID, T>>>(pp, b2s, h);
    }
    // ---- layer 3: out = log_softmax(A @ (relu(h) @ Wos) + bos) ----
    {
        const int NPB = 6 * 8;
        gemm_kernel<CC, P3S, 6, 8, true><<<(NN + NPB - 1) / NPB, dim3(CC, 6)>>>(h, Wos, (__half*)pp);
        spmm40_lsm_kernel<<<WARPS_GRID, T>>>(pp, bos, lsm);
    }
}

// round 5
// speedup vs baseline: 1.1493x; 1.1493x over previous
#include <cuda_runtime.h>
#include <cuda_fp16.h>
#include <math.h>

#define NN 100000
#define EE 1600000
#define FH 64      // input/hidden width
#define CC 40      // output classes
#define P3S 48     // padded layer-3 P row stride in halves (96 B = 3 sectors)

// ---------------- scratch (device globals; no allocation allowed) ----------
__device__ int   g_deg_out[NN];
__device__ int   g_deg_in[NN];
__device__ float g_invo[NN];
__device__ float g_invi[NN];
__device__ int   g_start[NN];              // CSR row start
__device__ int   g_pos[NN];                // bump cursor per row
__device__ unsigned g_csrc[EE];            // CSR col only (weights folded out)
__device__ unsigned int g_ctr;             // global bump counter
__device__ __half2 g_p[(size_t)NN * (FH / 2)];  // fp16 GEMM output (invi-scaled)
__device__ float g_y[(size_t)NN * FH];     // SpMM output layer 1

// ---------------- f32x2 packed-FMA helpers (Blackwell FFMA2) ----------------
__device__ __forceinline__ unsigned long long pack2f(float lo, float hi) {
    unsigned long long r;
    asm("mov.b64 %0, {%1, %2};" : "=l"(r) : "f"(lo), "f"(hi));
    return r;
}
__device__ __forceinline__ void fma2f(unsigned long long& d,
                                      unsigned long long a, unsigned long long b) {
    asm("fma.rn.f32x2 %0, %1, %2, %0;" : "+l"(d) : "l"(a), "l"(b));
}
__device__ __forceinline__ float2 unpack2f(unsigned long long v) {
    float lo, hi;
    asm("mov.b64 {%0, %1}, %2;" : "=f"(lo), "=f"(hi) : "l"(v));
    return make_float2(lo, hi);
}

// ---------------- zero -------------------------------------------------------
__global__ void zero_kernel() {
    int i = blockIdx.x * blockDim.x + threadIdx.x;
    if (i < NN) { g_deg_out[i] = 0; g_deg_in[i] = 0; }
    if (i == 0) g_ctr = 0u;
}

// ---------------- degree histogram ------------------------------------------
__global__ void hist_kernel(const int* __restrict__ row, const int* __restrict__ col) {
    int e = blockIdx.x * blockDim.x + threadIdx.x;
    if (e < EE) {
        atomicAdd(&g_deg_out[row[e]], 1);
        atomicAdd(&g_deg_in[col[e]], 1);
    }
}

// ---------------- range assignment (warp-aggregated bump alloc) + inv degs --
__global__ void ranges_kernel() {
    int i = blockIdx.x * blockDim.x + threadIdx.x;
    int lane = threadIdx.x & 31;
    int d = (i < NN) ? g_deg_out[i] : 0;
    int incl = d;
#pragma unroll
    for (int o = 1; o < 32; o <<= 1) {
        int v = __shfl_up_sync(0xffffffffu, incl, o);
        if (lane >= o) incl += v;
    }
    int total = __shfl_sync(0xffffffffu, incl, 31);
    unsigned int base = 0;
    if (lane == 31) base = atomicAdd(&g_ctr, (unsigned int)total);
    base = __shfl_sync(0xffffffffu, base, 31);
    if (i < NN) {
        int st = (int)base + (incl - d);
        g_start[i] = st;
        g_pos[i]   = st;
        int di = g_deg_in[i];
        g_invo[i] = (d  > 0) ? rsqrtf((float)d)  : 0.f;
        g_invi[i] = (di > 0) ? rsqrtf((float)di) : 0.f;
    }
}

// ---------------- edge scatter into CSR (col only, no float math) ------------
__global__ void scatter_kernel(const int* __restrict__ row, const int* __restrict__ col) {
    int e = blockIdx.x * blockDim.x + threadIdx.x;
    if (e >= EE) return;
    int r = row[e], c = col[e];
    int p = atomicAdd(&g_pos[r], 1);
    g_csrc[p] = (unsigned)c;
}

// ---------------- dense GEMM, software-pipelined -----------------------------
// P[N,OUT](fp16) = invi[n] * (relu?)X[N,64] @ W[64,OUT]
template <int OUT, int PSTRIDE, int YD, int TILES, bool RELU>
__global__ void gemm_kernel(const float* __restrict__ X,
                            const float* __restrict__ W,
                            __half* __restrict__ P) {
    __shared__ float sX[YD * FH];
    const int tx = threadIdx.x;            // 0..OUT-1
    const int ty = threadIdx.y;            // 0..YD-1
    const int tid = ty * OUT + tx;
    const int NT = OUT * YD;               // threads per block
    const int NE = YD * FH;                // elements per tile

    unsigned long long wp[FH / 2];
#pragma unroll
    for (int k2 = 0; k2 < FH / 2; k2++)
        wp[k2] = pack2f(W[(2 * k2) * OUT + tx], W[(2 * k2 + 1) * OUT + tx]);

    const int base = blockIdx.x * (YD * TILES);

    // prefetch tile 0 into registers
    float v0 = 0.f, v1 = 0.f;
    if (tid < NE) {
        int n = base + (tid >> 6);
        if (n < NN) v0 = X[(size_t)n * FH + (tid & 63)];
    }
    if (NT < NE && tid + NT < NE) {
        int n = base + ((tid + NT) >> 6);
        if (n < NN) v1 = X[(size_t)n * FH + ((tid + NT) & 63)];
    }

#pragma unroll 1
    for (int t = 0; t < TILES; t++) {
        // commit prefetched tile to smem (with fused relu)
        if (tid < NE) sX[tid] = RELU ? fmaxf(v0, 0.f) : v0;
        if (NT < NE && tid + NT < NE) sX[tid + NT] = RELU ? fmaxf(v1, 0.f) : v1;
        __syncthreads();
        // issue next tile's loads early (latency overlapped with compute below)
        if (t + 1 < TILES) {
            const int nb = base + (t + 1) * YD;
            v0 = 0.f; v1 = 0.f;
            if (tid < NE) {
                int n = nb + (tid >> 6);
                if (n < NN) v0 = X[(size_t)n * FH + (tid & 63)];
            }
            if (NT < NE && tid + NT < NE) {
                int n = nb + ((tid + NT) >> 6);
                if (n < NN) v1 = X[(size_t)n * FH + ((tid + NT) & 63)];
            }
        }
        const int n = base + t * YD + ty;
        if (n < NN) {
            const unsigned long long* sxd =
                reinterpret_cast<const unsigned long long*>(&sX[ty * FH]);
            unsigned long long acc0 = pack2f(0.f, 0.f);
            unsigned long long acc1 = pack2f(0.f, 0.f);
#pragma unroll
            for (int k2 = 0; k2 < FH / 2; k2 += 2) {
                fma2f(acc0, sxd[k2],     wp[k2]);
                fma2f(acc1, sxd[k2 + 1], wp[k2 + 1]);
            }
            float2 r0 = unpack2f(acc0);
            float2 r1 = unpack2f(acc1);
            float val = ((r0.x + r0.y) + (r1.x + r1.y)) * g_invi[n];
            P[(size_t)n * PSTRIDE + tx] = __float2half(val);
        }
        __syncthreads();
    }
}

// ---------------- gather SpMM, width 64: out = invo[n]*Σ P'[c] + bias --------
__global__ void spmm64_kernel(const __half2* __restrict__ P,
                              const float* __restrict__ bias,
                              float* __restrict__ Y) {
    int n = (blockIdx.x * blockDim.x + threadIdx.x) >> 5;
    int lane = threadIdx.x & 31;
    if (n >= NN) return;
    int s = g_start[n];
    int d = g_deg_out[n];
    float a0 = 0.f, a1 = 0.f, b0 = 0.f, b1 = 0.f;   // two accumulator pairs
    const unsigned* cs = g_csrc + s;
    int e = 0;
    for (; e + 8 <= d; e += 8) {
        unsigned c0 = cs[e],     c1 = cs[e + 1], c2 = cs[e + 2], c3 = cs[e + 3];
        unsigned c4 = cs[e + 4], c5 = cs[e + 5], c6 = cs[e + 6], c7 = cs[e + 7];
        float2 v0 = __half22float2(__ldg(P + (size_t)c0 * (FH / 2) + lane));
        float2 v1 = __half22float2(__ldg(P + (size_t)c1 * (FH / 2) + lane));
        float2 v2 = __half22float2(__ldg(P + (size_t)c2 * (FH / 2) + lane));
        float2 v3 = __half22float2(__ldg(P + (size_t)c3 * (FH / 2) + lane));
        float2 v4 = __half22float2(__ldg(P + (size_t)c4 * (FH / 2) + lane));
        float2 v5 = __half22float2(__ldg(P + (size_t)c5 * (FH / 2) + lane));
        float2 v6 = __half22float2(__ldg(P + (size_t)c6 * (FH / 2) + lane));
        float2 v7 = __half22float2(__ldg(P + (size_t)c7 * (FH / 2) + lane));
        a0 += v0.x; a1 += v0.y;  b0 += v1.x; b1 += v1.y;
        a0 += v2.x; a1 += v2.y;  b0 += v3.x; b1 += v3.y;
        a0 += v4.x; a1 += v4.y;  b0 += v5.x; b1 += v5.y;
        a0 += v6.x; a1 += v6.y;  b0 += v7.x; b1 += v7.y;
    }
    if (e + 4 <= d) {
        unsigned c0 = cs[e], c1 = cs[e + 1], c2 = cs[e + 2], c3 = cs[e + 3];
        float2 v0 = __half22float2(__ldg(P + (size_t)c0 * (FH / 2) + lane));
        float2 v1 = __half22float2(__ldg(P + (size_t)c1 * (FH / 2) + lane));
        float2 v2 = __half22float2(__ldg(P + (size_t)c2 * (FH / 2) + lane));
        float2 v3 = __half22float2(__ldg(P + (size_t)c3 * (FH / 2) + lane));
        a0 += v0.x; a1 += v0.y;  b0 += v1.x; b1 += v1.y;
        a0 += v2.x; a1 += v2.y;  b0 += v3.x; b1 += v3.y;
        e += 4;
    }
    for (; e < d; e++) {
        unsigned c0 = cs[e];
        float2 v0 = __half22float2(__ldg(P + (size_t)c0 * (FH / 2) + lane));
        a0 += v0.x; a1 += v0.y;
    }
    a0 += b0; a1 += b1;
    float inv = g_invo[n];
    float bb0 = bias[2 * lane], bb1 = bias[2 * lane + 1];
    *reinterpret_cast<float2*>(Y + (size_t)n * FH + 2 * lane) =
        make_float2(fmaf(inv, a0, bb0), fmaf(inv, a1, bb1));
}

// ---------------- gather SpMM width 40 (padded fp16 rows) + log-softmax ------
__global__ void spmm40_lsm_kernel(const __half2* __restrict__ P,
                                  const float* __restrict__ bias,
                                  float* __restrict__ O) {
    int n = (blockIdx.x * blockDim.x + threadIdx.x) >> 5;
    int lane = threadIdx.x & 31;
    if (n >= NN) return;
    int s = g_start[n];
    int d = g_deg_out[n];
    const bool act = (lane < CC / 2);   // lanes 0..19 own feature pairs
    float a0 = 0.f, a1 = 0.f, b0 = 0.f, b1 = 0.f;
    const unsigned* cs = g_csrc + s;
    int e = 0;
    for (; e + 4 <= d; e += 4) {
        unsigned c0 = cs[e], c1 = cs[e + 1], c2 = cs[e + 2], c3 = cs[e + 3];
        if (act) {
            float2 v0 = __half22float2(__ldg(P + (size_t)c0 * (P3S / 2) + lane));
            float2 v1 = __half22float2(__ldg(P + (size_t)c1 * (P3S / 2) + lane));
            float2 v2 = __half22float2(__ldg(P + (size_t)c2 * (P3S / 2) + lane));
            float2 v3 = __half22float2(__ldg(P + (size_t)c3 * (P3S / 2) + lane));
            a0 += v0.x; a1 += v0.y;  b0 += v1.x; b1 += v1.y;
            a0 += v2.x; a1 += v2.y;  b0 += v3.x; b1 += v3.y;
        }
    }
    for (; e < d; e++) {
        unsigned c0 = cs[e];
        if (act) {
            float2 v0 = __half22float2(__ldg(P + (size_t)c0 * (P3S / 2) + lane));
            a0 += v0.x; a1 += v0.y;
        }
    }
    a0 += b0; a1 += b1;
    float inv = g_invo[n];
    float t0 = act ? fmaf(inv, a0, bias[2 * lane])     : 0.f;
    float t1 = act ? fmaf(inv, a1, bias[2 * lane + 1]) : 0.f;
    // fused log-softmax over 40 values
    float m = act ? fmaxf(t0, t1) : -INFINITY;
#pragma unroll
    for (int o = 16; o; o >>= 1) m = fmaxf(m, __shfl_xor_sync(0xffffffffu, m, o));
    float sum = act ? (expf(t0 - m) + expf(t1 - m)) : 0.f;
#pragma unroll
    for (int o = 16; o; o >>= 1) sum += __shfl_xor_sync(0xffffffffu, sum, o);
    float ls = m + logf(sum);
    if (act) {
        *reinterpret_cast<float2*>(O + (size_t)n * CC + 2 * lane) =
            make_float2(t0 - ls, t1 - ls);
    }
}

// ---------------- launch -----------------------------------------------------
extern "C" void kernel_launch(void* const* d_in, const int* in_sizes, int n_in,
                              void* d_out, int out_size) {
    const float* x   = (const float*)d_in[0];
    const int*   ei  = (const int*)d_in[1];
    const int*   rowp = ei;
    const int*   colp = ei + EE;
    const float* W1s = (const float*)d_in[2];
    const float* b1s = (const float*)d_in[3];
    const float* W2s = (const float*)d_in[6];
    const float* b2s = (const float*)d_in[7];
    const float* Wos = (const float*)d_in[10];
    const float* bos = (const float*)d_in[11];

    float* out = (float*)d_out;
    float* h   = out;                       // [N, 64]
    float* lsm = out + (size_t)NN * FH;     // [N, 40]

    __half2* pp;
    float* py;
    cudaGetSymbolAddress((void**)&pp, g_p);
    cudaGetSymbolAddress((void**)&py, g_y);

    const int T = 256;

    // ---- CSR build (recomputed every call — determinism rule) ----
    zero_kernel<<<(NN + T - 1) / T, T>>>();
    hist_kernel<<<(EE + T - 1) / T, T>>>(rowp, colp);
    ranges_kernel<<<(NN + T - 1) / T, T>>>();
    scatter_kernel<<<(EE + T - 1) / T, T>>>(rowp, colp);

    const int WARPS_GRID = (NN * 32 + T - 1) / T;

    // ---- layer 1: x0 = A @ (x @ W1s) + b1s ----
    {
        const int NPB = 4 * 16;
        gemm_kernel<FH, FH, 4, 16, false><<<(NN + NPB - 1) / NPB, dim3(FH, 4)>>>(x, W1s, (__half*)pp);
        spmm64_kernel<<<WARPS_GRID, T>>>(pp, b1s, py);
    }
    // ---- layer 2: h = A @ (relu(x0) @ W2s) + b2s  (h -> d_out) ----
    {
        const int NPB = 4 * 16;
        gemm_kernel<FH, FH, 4, 16, true><<<(NN + NPB - 1) / NPB, dim3(FH, 4)>>>(py, W2s, (__half*)pp);
        spmm64_kernel<<<WARPS_GRID, T>>>(pp, b2s, h);
    }
    // ---- layer 3: out = log_softmax(A @ (relu(h) @ Wos) + bos) ----
    {
        const int NPB = 6 * 8;
        gemm_kernel<CC, P3S, 6, 8, true><<<(NN + NPB - 1) / NPB, dim3(CC, 6)>>>(h, Wos, (__half*)pp);
        spmm40_lsm_kernel<<<WARPS_GRID, T>>>(pp, bos, lsm);
    }
}

// round 6
// speedup vs baseline: 1.1998x; 1.0440x over previous
#include <cuda_runtime.h>
#include <cuda_fp16.h>
#include <math.h>

#define NN 100000
#define EE 1600000
#define FH 64      // input/hidden width
#define CC 40      // output classes
#define P3S 48     // padded layer-3 P row stride in halves (96 B = 3 sectors)

// ---------------- scratch (device globals; no allocation allowed) ----------
__device__ int   g_deg_out[NN];
__device__ int   g_deg_in[NN];
__device__ float g_invo[NN];
__device__ float g_invi[NN];
__device__ int   g_start[NN];              // CSR row start
__device__ int   g_pos[NN];                // bump cursor per row
__device__ unsigned g_csrc[EE];            // CSR col only (weights folded out)
__device__ unsigned int g_ctr;             // global bump counter
__device__ __half2 g_p[(size_t)NN * (FH / 2)];  // fp16 GEMM output (invi-scaled)
__device__ float g_y[(size_t)NN * FH];     // SpMM output layer 1

// ---------------- f32x2 packed-FMA helpers (Blackwell FFMA2) ----------------
__device__ __forceinline__ unsigned long long pack2f(float lo, float hi) {
    unsigned long long r;
    asm("mov.b64 %0, {%1, %2};" : "=l"(r) : "f"(lo), "f"(hi));
    return r;
}
__device__ __forceinline__ void fma2f(unsigned long long& d,
                                      unsigned long long a, unsigned long long b) {
    asm("fma.rn.f32x2 %0, %1, %2, %0;" : "+l"(d) : "l"(a), "l"(b));
}
__device__ __forceinline__ float2 unpack2f(unsigned long long v) {
    float lo, hi;
    asm("mov.b64 {%0, %1}, %2;" : "=f"(lo), "=f"(hi) : "l"(v));
    return make_float2(lo, hi);
}

// ---------------- zero -------------------------------------------------------
__global__ void zero_kernel() {
    int i = blockIdx.x * blockDim.x + threadIdx.x;
    if (i < NN) { g_deg_out[i] = 0; g_deg_in[i] = 0; }
    if (i == 0) g_ctr = 0u;
}

// ---------------- degree histogram (4 edges/thread, int4 loads) --------------
__global__ void hist_kernel(const int4* __restrict__ row4, const int4* __restrict__ col4) {
    int q = blockIdx.x * blockDim.x + threadIdx.x;
    if (q >= EE / 4) return;
    int4 r = row4[q];
    int4 c = col4[q];
    atomicAdd(&g_deg_out[r.x], 1); atomicAdd(&g_deg_out[r.y], 1);
    atomicAdd(&g_deg_out[r.z], 1); atomicAdd(&g_deg_out[r.w], 1);
    atomicAdd(&g_deg_in[c.x], 1);  atomicAdd(&g_deg_in[c.y], 1);
    atomicAdd(&g_deg_in[c.z], 1);  atomicAdd(&g_deg_in[c.w], 1);
}

// ---------------- range assignment (warp-aggregated bump alloc) + inv degs --
__global__ void ranges_kernel() {
    int i = blockIdx.x * blockDim.x + threadIdx.x;
    int lane = threadIdx.x & 31;
    int d = (i < NN) ? g_deg_out[i] : 0;
    int incl = d;
#pragma unroll
    for (int o = 1; o < 32; o <<= 1) {
        int v = __shfl_up_sync(0xffffffffu, incl, o);
        if (lane >= o) incl += v;
    }
    int total = __shfl_sync(0xffffffffu, incl, 31);
    unsigned int base = 0;
    if (lane == 31) base = atomicAdd(&g_ctr, (unsigned int)total);
    base = __shfl_sync(0xffffffffu, base, 31);
    if (i < NN) {
        int st = (int)base + (incl - d);
        g_start[i] = st;
        g_pos[i]   = st;
        int di = g_deg_in[i];
        g_invo[i] = (d  > 0) ? rsqrtf((float)d)  : 0.f;
        g_invi[i] = (di > 0) ? rsqrtf((float)di) : 0.f;
    }
}

// ---------------- edge scatter into CSR (4 edges/thread, col only) ----------
__global__ void scatter_kernel(const int4* __restrict__ row4, const int4* __restrict__ col4) {
    int q = blockIdx.x * blockDim.x + threadIdx.x;
    if (q >= EE / 4) return;
    int4 r = row4[q];
    int4 c = col4[q];
    g_csrc[atomicAdd(&g_pos[r.x], 1)] = (unsigned)c.x;
    g_csrc[atomicAdd(&g_pos[r.y], 1)] = (unsigned)c.y;
    g_csrc[atomicAdd(&g_pos[r.z], 1)] = (unsigned)c.z;
    g_csrc[atomicAdd(&g_pos[r.w], 1)] = (unsigned)c.w;
}

// ---------------- dense GEMM, software-pipelined -----------------------------
// P[N,OUT](fp16) = invi[n] * (relu?)X[N,64] @ W[64,OUT]
template <int OUT, int PSTRIDE, int YD, int TILES, bool RELU>
__global__ void gemm_kernel(const float* __restrict__ X,
                            const float* __restrict__ W,
                            __half* __restrict__ P) {
    __shared__ float sX[YD * FH];
    const int tx = threadIdx.x;            // 0..OUT-1
    const int ty = threadIdx.y;            // 0..YD-1
    const int tid = ty * OUT + tx;
    const int NT = OUT * YD;               // threads per block
    const int NE = YD * FH;                // elements per tile

    unsigned long long wp[FH / 2];
#pragma unroll
    for (int k2 = 0; k2 < FH / 2; k2++)
        wp[k2] = pack2f(W[(2 * k2) * OUT + tx], W[(2 * k2 + 1) * OUT + tx]);

    const int base = blockIdx.x * (YD * TILES);

    // prefetch tile 0 into registers
    float v0 = 0.f, v1 = 0.f;
    if (tid < NE) {
        int n = base + (tid >> 6);
        if (n < NN) v0 = X[(size_t)n * FH + (tid & 63)];
    }
    if (NT < NE && tid + NT < NE) {
        int n = base + ((tid + NT) >> 6);
        if (n < NN) v1 = X[(size_t)n * FH + ((tid + NT) & 63)];
    }

#pragma unroll 1
    for (int t = 0; t < TILES; t++) {
        if (tid < NE) sX[tid] = RELU ? fmaxf(v0, 0.f) : v0;
        if (NT < NE && tid + NT < NE) sX[tid + NT] = RELU ? fmaxf(v1, 0.f) : v1;
        __syncthreads();
        if (t + 1 < TILES) {
            const int nb = base + (t + 1) * YD;
            v0 = 0.f; v1 = 0.f;
            if (tid < NE) {
                int n = nb + (tid >> 6);
                if (n < NN) v0 = X[(size_t)n * FH + (tid & 63)];
            }
            if (NT < NE && tid + NT < NE) {
                int n = nb + ((tid + NT) >> 6);
                if (n < NN) v1 = X[(size_t)n * FH + ((tid + NT) & 63)];
            }
        }
        const int n = base + t * YD + ty;
        if (n < NN) {
            const unsigned long long* sxd =
                reinterpret_cast<const unsigned long long*>(&sX[ty * FH]);
            unsigned long long acc0 = pack2f(0.f, 0.f);
            unsigned long long acc1 = pack2f(0.f, 0.f);
#pragma unroll
            for (int k2 = 0; k2 < FH / 2; k2 += 2) {
                fma2f(acc0, sxd[k2],     wp[k2]);
                fma2f(acc1, sxd[k2 + 1], wp[k2 + 1]);
            }
            float2 r0 = unpack2f(acc0);
            float2 r1 = unpack2f(acc1);
            float val = ((r0.x + r0.y) + (r1.x + r1.y)) * g_invi[n];
            P[(size_t)n * PSTRIDE + tx] = __float2half(val);
        }
        __syncthreads();
    }
}

// ---------------- half-warp gather SpMM, width 64 ----------------------------
// Each 16-lane half processes one edge per step with LDG.64 (4 features/lane).
__device__ __forceinline__ void acc4(float& a0, float& a1, float& a2, float& a3,
                                     uint2 v) {
    __half2 h0 = *reinterpret_cast<__half2*>(&v.x);
    __half2 h1 = *reinterpret_cast<__half2*>(&v.y);
    float2 f0 = __half22float2(h0);
    float2 f1 = __half22float2(h1);
    a0 += f0.x; a1 += f0.y; a2 += f1.x; a3 += f1.y;
}

__global__ void spmm64_kernel(const uint2* __restrict__ P,   // rows of 16 uint2
                              const float* __restrict__ bias,
                              float* __restrict__ Y) {
    int n = (blockIdx.x * blockDim.x + threadIdx.x) >> 5;
    int lane = threadIdx.x & 31;
    if (n >= NN) return;
    int s = g_start[n];
    int d = g_deg_out[n];
    const int half = lane >> 4;
    const int l16  = lane & 15;
    const unsigned* cs = g_csrc + s;
    float a0 = 0.f, a1 = 0.f, a2 = 0.f, a3 = 0.f;
    int e = 0;
    for (; e + 8 <= d; e += 8) {                // 8 edges: 4 gathers in flight
        unsigned cA = cs[e     + half];
        unsigned cB = cs[e + 2 + half];
        unsigned cC = cs[e + 4 + half];
        unsigned cD = cs[e + 6 + half];
        uint2 vA = __ldg(P + cA * 16u + l16);
        uint2 vB = __ldg(P + cB * 16u + l16);
        uint2 vC = __ldg(P + cC * 16u + l16);
        uint2 vD = __ldg(P + cD * 16u + l16);
        acc4(a0, a1, a2, a3, vA);
        acc4(a0, a1, a2, a3, vB);
        acc4(a0, a1, a2, a3, vC);
        acc4(a0, a1, a2, a3, vD);
    }
    for (; e + 2 <= d; e += 2) {
        unsigned c = cs[e + half];
        uint2 v = __ldg(P + c * 16u + l16);
        acc4(a0, a1, a2, a3, v);
    }
    if (e < d && half == 0) {                   // odd tail: half 0 only
        unsigned c = cs[e];
        uint2 v = __ldg(P + c * 16u + l16);
        acc4(a0, a1, a2, a3, v);
    }
    // combine the two halves
    a0 += __shfl_xor_sync(0xffffffffu, a0, 16);
    a1 += __shfl_xor_sync(0xffffffffu, a1, 16);
    a2 += __shfl_xor_sync(0xffffffffu, a2, 16);
    a3 += __shfl_xor_sync(0xffffffffu, a3, 16);
    if (half == 0) {
        float inv = g_invo[n];
        const float4 bb = *reinterpret_cast<const float4*>(bias + 4 * l16);
        float4 r;
        r.x = fmaf(inv, a0, bb.x);
        r.y = fmaf(inv, a1, bb.y);
        r.z = fmaf(inv, a2, bb.z);
        r.w = fmaf(inv, a3, bb.w);
        *reinterpret_cast<float4*>(Y + (size_t)n * FH + 4 * l16) = r;
    }
}

// ---------------- gather SpMM width 40 (padded fp16 rows) + log-softmax ------
__global__ void spmm40_lsm_kernel(const __half2* __restrict__ P,
                                  const float* __restrict__ bias,
                                  float* __restrict__ O) {
    int n = (blockIdx.x * blockDim.x + threadIdx.x) >> 5;
    int lane = threadIdx.x & 31;
    if (n >= NN) return;
    int s = g_start[n];
    int d = g_deg_out[n];
    const bool act = (lane < CC / 2);   // lanes 0..19 own feature pairs
    float a0 = 0.f, a1 = 0.f, b0 = 0.f, b1 = 0.f;
    const unsigned* cs = g_csrc + s;
    int e = 0;
    for (; e + 4 <= d; e += 4) {
        unsigned c0 = cs[e], c1 = cs[e + 1], c2 = cs[e + 2], c3 = cs[e + 3];
        if (act) {
            float2 v0 = __half22float2(__ldg(P + c0 * (unsigned)(P3S / 2) + lane));
            float2 v1 = __half22float2(__ldg(P + c1 * (unsigned)(P3S / 2) + lane));
            float2 v2 = __half22float2(__ldg(P + c2 * (unsigned)(P3S / 2) + lane));
            float2 v3 = __half22float2(__ldg(P + c3 * (unsigned)(P3S / 2) + lane));
            a0 += v0.x; a1 += v0.y;  b0 += v1.x; b1 += v1.y;
            a0 += v2.x; a1 += v2.y;  b0 += v3.x; b1 += v3.y;
        }
    }
    for (; e < d; e++) {
        unsigned c0 = cs[e];
        if (act) {
            float2 v0 = __half22float2(__ldg(P + c0 * (unsigned)(P3S / 2) + lane));
            a0 += v0.x; a1 += v0.y;
        }
    }
    a0 += b0; a1 += b1;
    float inv = g_invo[n];
    float t0 = act ? fmaf(inv, a0, bias[2 * lane])     : 0.f;
    float t1 = act ? fmaf(inv, a1, bias[2 * lane + 1]) : 0.f;
    float m = act ? fmaxf(t0, t1) : -INFINITY;
#pragma unroll
    for (int o = 16; o; o >>= 1) m = fmaxf(m, __shfl_xor_sync(0xffffffffu, m, o));
    float sum = act ? (expf(t0 - m) + expf(t1 - m)) : 0.f;
#pragma unroll
    for (int o = 16; o; o >>= 1) sum += __shfl_xor_sync(0xffffffffu, sum, o);
    float ls = m + logf(sum);
    if (act) {
        *reinterpret_cast<float2*>(O + (size_t)n * CC + 2 * lane) =
            make_float2(t0 - ls, t1 - ls);
    }
}

// ---------------- launch -----------------------------------------------------
extern "C" void kernel_launch(void* const* d_in, const int* in_sizes, int n_in,
                              void* d_out, int out_size) {
    const float* x   = (const float*)d_in[0];
    const int*   ei  = (const int*)d_in[1];
    const int4*  row4 = (const int4*)ei;
    const int4*  col4 = (const int4*)(ei + EE);
    const float* W1s = (const float*)d_in[2];
    const float* b1s = (const float*)d_in[3];
    const float* W2s = (const float*)d_in[6];
    const float* b2s = (const float*)d_in[7];
    const float* Wos = (const float*)d_in[10];
    const float* bos = (const float*)d_in[11];

    float* out = (float*)d_out;
    float* h   = out;                       // [N, 64]
    float* lsm = out + (size_t)NN * FH;     // [N, 40]

    __half2* pp;
    float* py;
    cudaGetSymbolAddress((void**)&pp, g_p);
    cudaGetSymbolAddress((void**)&py, g_y);

    const int T = 256;
    const int WARPS_GRID = (NN * 32 + T - 1) / T;
    const int NPB64 = 4 * 16;
    const int Q = EE / 4;

    // ---- CSR build + layer-1 GEMM interleaved (gemm1 only needs ranges) ----
    zero_kernel<<<(NN + T - 1) / T, T>>>();
    hist_kernel<<<(Q + T - 1) / T, T>>>(row4, col4);
    ranges_kernel<<<(NN + T - 1) / T, T>>>();
    gemm_kernel<FH, FH, 4, 16, false><<<(NN + NPB64 - 1) / NPB64, dim3(FH, 4)>>>(x, W1s, (__half*)pp);
    scatter_kernel<<<(Q + T - 1) / T, T>>>(row4, col4);

    // ---- layer 1 aggregate ----
    spmm64_kernel<<<WARPS_GRID, T>>>((const uint2*)pp, b1s, py);
    // ---- layer 2: h = A @ (relu(x0) @ W2s) + b2s  (h -> d_out) ----
    gemm_kernel<FH, FH, 4, 16, true><<<(NN + NPB64 - 1) / NPB64, dim3(FH, 4)>>>(py, W2s, (__half*)pp);
    spmm64_kernel<<<WARPS_GRID, T>>>((const uint2*)pp, b2s, h);
    // ---- layer 3: out = log_softmax(A @ (relu(h) @ Wos) + bos) ----
    {
        const int NPB = 6 * 8;
        gemm_kernel<CC, P3S, 6, 8, true><<<(NN + NPB - 1) / NPB, dim3(CC, 6)>>>(h, Wos, (__half*)pp);
        spmm40_lsm_kernel<<<WARPS_GRID, T>>>(pp, bos, lsm);
    }
}

// round 7
// speedup vs baseline: 1.6449x; 1.3710x over previous
#include <cuda_runtime.h>
#include <cuda_fp16.h>
#include <math.h>

#define NN 100000
#define EE 1600000
#define FH 64      // input/hidden width
#define CC 40      // output classes
#define P3S 48     // padded layer-3 P row stride in halves (96 B = 3 sectors)

// ---------------- scratch (device globals; no allocation allowed) ----------
__device__ int   g_deg_out[NN];
__device__ int   g_deg_in[NN];
__device__ float g_invo[NN];
__device__ float g_invi[NN];
__device__ int   g_start[NN];              // CSR row start
__device__ int   g_pos[NN];                // bump cursor per row
__device__ unsigned g_csrc[EE];            // CSR col only (weights folded out)
__device__ unsigned int g_ctr;             // global bump counter
__device__ __half g_p[(size_t)NN * FH];    // fp16 GEMM output (invi-scaled)
__device__ __half g_xh[(size_t)NN * FH];   // fp16 relu'd SpMM output (next GEMM in)
__device__ __half g_w1h[FH * FH];          // W1 fp16 n-major [n][k]
__device__ __half g_w2h[FH * FH];          // W2 fp16 n-major
__device__ __half g_w3h[CC * FH];          // Wo fp16 n-major

// ---------------- zero + weight convert (blocks 0-2 convert W -> fp16 n-major)
__global__ void zero_kernel(const float* __restrict__ W1,
                            const float* __restrict__ W2,
                            const float* __restrict__ W3) {
    int i = blockIdx.x * blockDim.x + threadIdx.x;
    if (i < NN) { g_deg_out[i] = 0; g_deg_in[i] = 0; }
    if (i == 0) g_ctr = 0u;
    if (blockIdx.x < 3) {
        const float* Ws = (blockIdx.x == 0) ? W1 : (blockIdx.x == 1) ? W2 : W3;
        __half* dst = (blockIdx.x == 0) ? g_w1h : (blockIdx.x == 1) ? g_w2h : g_w3h;
        int outw = (blockIdx.x == 2) ? CC : FH;
        for (int idx = threadIdx.x; idx < outw * FH; idx += blockDim.x) {
            int n = idx >> 6, k = idx & 63;
            dst[idx] = __float2half(Ws[k * outw + n]);   // Wt[n][k] = W[k][n]
        }
    }
}

// ---------------- degree histogram (4 edges/thread, int4 loads) --------------
__global__ void hist_kernel(const int4* __restrict__ row4, const int4* __restrict__ col4) {
    int q = blockIdx.x * blockDim.x + threadIdx.x;
    if (q >= EE / 4) return;
    int4 r = row4[q];
    int4 c = col4[q];
    atomicAdd(&g_deg_out[r.x], 1); atomicAdd(&g_deg_out[r.y], 1);
    atomicAdd(&g_deg_out[r.z], 1); atomicAdd(&g_deg_out[r.w], 1);
    atomicAdd(&g_deg_in[c.x], 1);  atomicAdd(&g_deg_in[c.y], 1);
    atomicAdd(&g_deg_in[c.z], 1);  atomicAdd(&g_deg_in[c.w], 1);
}

// ---------------- range assignment (warp-aggregated bump alloc) + inv degs --
__global__ void ranges_kernel() {
    int i = blockIdx.x * blockDim.x + threadIdx.x;
    int lane = threadIdx.x & 31;
    int d = (i < NN) ? g_deg_out[i] : 0;
    int incl = d;
#pragma unroll
    for (int o = 1; o < 32; o <<= 1) {
        int v = __shfl_up_sync(0xffffffffu, incl, o);
        if (lane >= o) incl += v;
    }
    int total = __shfl_sync(0xffffffffu, incl, 31);
    unsigned int base = 0;
    if (lane == 31) base = atomicAdd(&g_ctr, (unsigned int)total);
    base = __shfl_sync(0xffffffffu, base, 31);
    if (i < NN) {
        int st = (int)base + (incl - d);
        g_start[i] = st;
        g_pos[i]   = st;
        int di = g_deg_in[i];
        g_invo[i] = (d  > 0) ? rsqrtf((float)d)  : 0.f;
        g_invi[i] = (di > 0) ? rsqrtf((float)di) : 0.f;
    }
}

// ---------------- edge scatter into CSR (4 edges/thread, col only) ----------
__global__ void scatter_kernel(const int4* __restrict__ row4, const int4* __restrict__ col4) {
    int q = blockIdx.x * blockDim.x + threadIdx.x;
    if (q >= EE / 4) return;
    int4 r = row4[q];
    int4 c = col4[q];
    g_csrc[atomicAdd(&g_pos[r.x], 1)] = (unsigned)c.x;
    g_csrc[atomicAdd(&g_pos[r.y], 1)] = (unsigned)c.y;
    g_csrc[atomicAdd(&g_pos[r.z], 1)] = (unsigned)c.z;
    g_csrc[atomicAdd(&g_pos[r.w], 1)] = (unsigned)c.w;
}

// ---------------- tensor-core GEMM ------------------------------------------
// P[N,OUT](fp16) = invi[n] * X[N,64] @ W[64,OUT], via mma.sync m16n8k16.
// One warp per 16-row tile. Wt is fp16 n-major [OUT][64].
__device__ __forceinline__ void mma16816(float c[4], unsigned a0, unsigned a1,
                                         unsigned a2, unsigned a3,
                                         unsigned b0, unsigned b1) {
    asm volatile(
        "mma.sync.aligned.m16n8k16.row.col.f32.f16.f16.f32 "
        "{%0,%1,%2,%3}, {%4,%5,%6,%7}, {%8,%9}, {%0,%1,%2,%3};\n"
        : "+f"(c[0]), "+f"(c[1]), "+f"(c[2]), "+f"(c[3])
        : "r"(a0), "r"(a1), "r"(a2), "r"(a3), "r"(b0), "r"(b1));
}

template <int OUT, int PSTRIDE, bool F32IN>
__global__ void gemm_mma_kernel(const void* __restrict__ Xin,
                                const __half* __restrict__ Wt,
                                __half* __restrict__ P) {
    const int w = threadIdx.x >> 5, lane = threadIdx.x & 31;
    const int tile = blockIdx.x * 4 + w;
    const int row0 = tile * 16;
    if (row0 >= NN) return;
    const int g = lane >> 2, tg = lane & 3;
    const int r1 = row0 + g, r2 = row0 + g + 8;
    constexpr int NT = OUT / 8;

    float acc[NT][4];
#pragma unroll
    for (int nt = 0; nt < NT; nt++) {
        acc[nt][0] = 0.f; acc[nt][1] = 0.f; acc[nt][2] = 0.f; acc[nt][3] = 0.f;
    }

#pragma unroll
    for (int ks = 0; ks < 4; ks++) {
        const int k0 = ks * 16 + tg * 2;
        unsigned a0, a1, a2, a3;
        if (F32IN) {
            const float* X = (const float*)Xin;
            float2 f0 = *(const float2*)(X + (size_t)r1 * FH + k0);
            float2 f1 = *(const float2*)(X + (size_t)r2 * FH + k0);
            float2 f2 = *(const float2*)(X + (size_t)r1 * FH + k0 + 8);
            float2 f3 = *(const float2*)(X + (size_t)r2 * FH + k0 + 8);
            __half2 h0 = __floats2half2_rn(f0.x, f0.y);
            __half2 h1 = __floats2half2_rn(f1.x, f1.y);
            __half2 h2 = __floats2half2_rn(f2.x, f2.y);
            __half2 h3 = __floats2half2_rn(f3.x, f3.y);
            a0 = *(unsigned*)&h0; a1 = *(unsigned*)&h1;
            a2 = *(unsigned*)&h2; a3 = *(unsigned*)&h3;
        } else {
            const __half* Xh = (const __half*)Xin;
            a0 = *(const unsigned*)(Xh + (size_t)r1 * FH + k0);
            a1 = *(const unsigned*)(Xh + (size_t)r2 * FH + k0);
            a2 = *(const unsigned*)(Xh + (size_t)r1 * FH + k0 + 8);
            a3 = *(const unsigned*)(Xh + (size_t)r2 * FH + k0 + 8);
        }
#pragma unroll
        for (int nt = 0; nt < NT; nt++) {
            unsigned b0 = *(const unsigned*)(Wt + (nt * 8 + g) * FH + k0);
            unsigned b1 = *(const unsigned*)(Wt + (nt * 8 + g) * FH + k0 + 8);
            mma16816(acc[nt], a0, a1, a2, a3, b0, b1);
        }
    }

    const float inv1 = g_invi[r1], inv2 = g_invi[r2];
#pragma unroll
    for (int nt = 0; nt < NT; nt++) {
        __half2 h1 = __floats2half2_rn(acc[nt][0] * inv1, acc[nt][1] * inv1);
        __half2 h2 = __floats2half2_rn(acc[nt][2] * inv2, acc[nt][3] * inv2);
        *(__half2*)(P + (size_t)r1 * PSTRIDE + nt * 8 + tg * 2) = h1;
        *(__half2*)(P + (size_t)r2 * PSTRIDE + nt * 8 + tg * 2) = h2;
    }
}

// ---------------- half-warp gather SpMM, width 64 ----------------------------
__device__ __forceinline__ void acc4(float& a0, float& a1, float& a2, float& a3,
                                     uint2 v) {
    __half2 h0 = *reinterpret_cast<__half2*>(&v.x);
    __half2 h1 = *reinterpret_cast<__half2*>(&v.y);
    float2 f0 = __half22float2(h0);
    float2 f1 = __half22float2(h1);
    a0 += f0.x; a1 += f0.y; a2 += f1.x; a3 += f1.y;
}

// WRITE32: also write fp32 result to Y (layer 2 -> d_out h). Always writes
// fp16 relu'd copy to g_xh (input of next GEMM).
template <bool WRITE32>
__global__ void spmm64_kernel(const uint2* __restrict__ P,   // rows of 16 uint2
                              const float* __restrict__ bias,
                              float* __restrict__ Y) {
    int n = (blockIdx.x * blockDim.x + threadIdx.x) >> 5;
    int lane = threadIdx.x & 31;
    if (n >= NN) return;
    int s = g_start[n];
    int d = g_deg_out[n];
    const int half = lane >> 4;
    const int l16  = lane & 15;
    const unsigned* cs = g_csrc + s;
    float a0 = 0.f, a1 = 0.f, a2 = 0.f, a3 = 0.f;
    int e = 0;
    for (; e + 8 <= d; e += 8) {
        unsigned cA = cs[e     + half];
        unsigned cB = cs[e + 2 + half];
        unsigned cC = cs[e + 4 + half];
        unsigned cD = cs[e + 6 + half];
        uint2 vA = __ldg(P + cA * 16u + l16);
        uint2 vB = __ldg(P + cB * 16u + l16);
        uint2 vC = __ldg(P + cC * 16u + l16);
        uint2 vD = __ldg(P + cD * 16u + l16);
        acc4(a0, a1, a2, a3, vA);
        acc4(a0, a1, a2, a3, vB);
        acc4(a0, a1, a2, a3, vC);
        acc4(a0, a1, a2, a3, vD);
    }
    for (; e + 2 <= d; e += 2) {
        unsigned c = cs[e + half];
        uint2 v = __ldg(P + c * 16u + l16);
        acc4(a0, a1, a2, a3, v);
    }
    if (e < d && half == 0) {
        unsigned c = cs[e];
        uint2 v = __ldg(P + c * 16u + l16);
        acc4(a0, a1, a2, a3, v);
    }
    a0 += __shfl_xor_sync(0xffffffffu, a0, 16);
    a1 += __shfl_xor_sync(0xffffffffu, a1, 16);
    a2 += __shfl_xor_sync(0xffffffffu, a2, 16);
    a3 += __shfl_xor_sync(0xffffffffu, a3, 16);
    if (half == 0) {
        float inv = g_invo[n];
        const float4 bb = *reinterpret_cast<const float4*>(bias + 4 * l16);
        float r0 = fmaf(inv, a0, bb.x);
        float r1 = fmaf(inv, a1, bb.y);
        float r2 = fmaf(inv, a2, bb.z);
        float r3 = fmaf(inv, a3, bb.w);
        if (WRITE32) {
            *reinterpret_cast<float4*>(Y + (size_t)n * FH + 4 * l16) =
                make_float4(r0, r1, r2, r3);
        }
        __half2 q0 = __floats2half2_rn(fmaxf(r0, 0.f), fmaxf(r1, 0.f));
        __half2 q1 = __floats2half2_rn(fmaxf(r2, 0.f), fmaxf(r3, 0.f));
        uint2 q = make_uint2(*(unsigned*)&q0, *(unsigned*)&q1);
        *reinterpret_cast<uint2*>(g_xh + (size_t)n * FH + 4 * l16) = q;
    }
}

// ---------------- gather SpMM width 40 (padded fp16 rows) + log-softmax ------
__global__ void spmm40_lsm_kernel(const __half2* __restrict__ P,
                                  const float* __restrict__ bias,
                                  float* __restrict__ O) {
    int n = (blockIdx.x * blockDim.x + threadIdx.x) >> 5;
    int lane = threadIdx.x & 31;
    if (n >= NN) return;
    int s = g_start[n];
    int d = g_deg_out[n];
    const bool act = (lane < CC / 2);   // lanes 0..19 own feature pairs
    float a0 = 0.f, a1 = 0.f, b0 = 0.f, b1 = 0.f;
    const unsigned* cs = g_csrc + s;
    int e = 0;
    for (; e + 4 <= d; e += 4) {
        unsigned c0 = cs[e], c1 = cs[e + 1], c2 = cs[e + 2], c3 = cs[e + 3];
        if (act) {
            float2 v0 = __half22float2(__ldg(P + c0 * (unsigned)(P3S / 2) + lane));
            float2 v1 = __half22float2(__ldg(P + c1 * (unsigned)(P3S / 2) + lane));
            float2 v2 = __half22float2(__ldg(P + c2 * (unsigned)(P3S / 2) + lane));
            float2 v3 = __half22float2(__ldg(P + c3 * (unsigned)(P3S / 2) + lane));
            a0 += v0.x; a1 += v0.y;  b0 += v1.x; b1 += v1.y;
            a0 += v2.x; a1 += v2.y;  b0 += v3.x; b1 += v3.y;
        }
    }
    for (; e < d; e++) {
        unsigned c0 = cs[e];
        if (act) {
            float2 v0 = __half22float2(__ldg(P + c0 * (unsigned)(P3S / 2) + lane));
            a0 += v0.x; a1 += v0.y;
        }
    }
    a0 += b0; a1 += b1;
    float inv = g_invo[n];
    float t0 = act ? fmaf(inv, a0, bias[2 * lane])     : 0.f;
    float t1 = act ? fmaf(inv, a1, bias[2 * lane + 1]) : 0.f;
    float m = act ? fmaxf(t0, t1) : -INFINITY;
#pragma unroll
    for (int o = 16; o; o >>= 1) m = fmaxf(m, __shfl_xor_sync(0xffffffffu, m, o));
    float sum = act ? (expf(t0 - m) + expf(t1 - m)) : 0.f;
#pragma unroll
    for (int o = 16; o; o >>= 1) sum += __shfl_xor_sync(0xffffffffu, sum, o);
    float ls = m + logf(sum);
    if (act) {
        *reinterpret_cast<float2*>(O + (size_t)n * CC + 2 * lane) =
            make_float2(t0 - ls, t1 - ls);
    }
}

// ---------------- launch -----------------------------------------------------
extern "C" void kernel_launch(void* const* d_in, const int* in_sizes, int n_in,
                              void* d_out, int out_size) {
    const float* x   = (const float*)d_in[0];
    const int*   ei  = (const int*)d_in[1];
    const int4*  row4 = (const int4*)ei;
    const int4*  col4 = (const int4*)(ei + EE);
    const float* W1s = (const float*)d_in[2];
    const float* b1s = (const float*)d_in[3];
    const float* W2s = (const float*)d_in[6];
    const float* b2s = (const float*)d_in[7];
    const float* Wos = (const float*)d_in[10];
    const float* bos = (const float*)d_in[11];

    float* out = (float*)d_out;
    float* h   = out;                       // [N, 64]
    float* lsm = out + (size_t)NN * FH;     // [N, 40]

    __half *pp, *pxh, *pw1, *pw2, *pw3;
    cudaGetSymbolAddress((void**)&pp,  g_p);
    cudaGetSymbolAddress((void**)&pxh, g_xh);
    cudaGetSymbolAddress((void**)&pw1, g_w1h);
    cudaGetSymbolAddress((void**)&pw2, g_w2h);
    cudaGetSymbolAddress((void**)&pw3, g_w3h);

    const int T = 256;
    const int WARPS_GRID = (NN * 32 + T - 1) / T;
    const int Q = EE / 4;
    const int GEMM_GRID = (NN / 16 + 3) / 4;   // 4 warp-tiles of 16 rows per block

    // ---- CSR build + weight conversion; gemm1 in profile slot 4 ----
    zero_kernel<<<(NN + T - 1) / T, T>>>(W1s, W2s, Wos);
    hist_kernel<<<(Q + T - 1) / T, T>>>(row4, col4);
    ranges_kernel<<<(NN + T - 1) / T, T>>>();
    gemm_mma_kernel<FH, FH, true><<<GEMM_GRID, 128>>>(x, pw1, pp);
    scatter_kernel<<<(Q + T - 1) / T, T>>>(row4, col4);

    // ---- layer 1 aggregate (writes fp16 relu to g_xh only) ----
    spmm64_kernel<false><<<WARPS_GRID, T>>>((const uint2*)pp, b1s, h);
    // ---- layer 2 ----
    gemm_mma_kernel<FH, FH, false><<<GEMM_GRID, 128>>>(pxh, pw2, pp);
    spmm64_kernel<true><<<WARPS_GRID, T>>>((const uint2*)pp, b2s, h);
    // ---- layer 3 ----
    gemm_mma_kernel<CC, P3S, false><<<GEMM_GRID, 128>>>(pxh, pw3, pp);
    spmm40_lsm_kernel<<<WARPS_GRID, T>>>((const __half2*)pp, bos, lsm);
}

// round 8
// speedup vs baseline: 1.6742x; 1.0178x over previous
#include <cuda_runtime.h>
#include <cuda_fp16.h>
#include <math.h>

#define NN 100000
#define EE 1600000
#define FH 64      // input/hidden width
#define CC 40      // output classes
#define P3S 48     // padded layer-3 P row stride in halves (96 B = 3 sectors)

// ---------------- scratch (device globals; no allocation allowed) ----------
__device__ int   g_deg_out[NN];
__device__ int   g_deg_in[NN];
__device__ float g_invo[NN];
__device__ float g_invi[NN];
__device__ int   g_start[NN];              // CSR row start
__device__ int   g_pos[NN];                // bump cursor per row
__device__ unsigned g_csrc[EE];            // CSR col only (weights folded out)
__device__ unsigned int g_ctr;             // global bump counter
__device__ __half g_p[(size_t)NN * FH];    // fp16 GEMM output (invi-scaled)
__device__ __half g_xh[(size_t)NN * FH];   // fp16 relu'd SpMM output (next GEMM in)
__device__ __half g_w1h[FH * FH];          // W1 fp16 n-major [n][k]
__device__ __half g_w2h[FH * FH];          // W2 fp16 n-major
__device__ __half g_w3h[CC * FH];          // Wo fp16 n-major

// ---------------- zero + weight convert (blocks 0-2 convert W -> fp16 n-major)
__global__ void zero_kernel(const float* __restrict__ W1,
                            const float* __restrict__ W2,
                            const float* __restrict__ W3) {
    int i = blockIdx.x * blockDim.x + threadIdx.x;
    if (i < NN) { g_deg_out[i] = 0; g_deg_in[i] = 0; }
    if (i == 0) g_ctr = 0u;
    if (blockIdx.x < 3) {
        const float* Ws = (blockIdx.x == 0) ? W1 : (blockIdx.x == 1) ? W2 : W3;
        __half* dst = (blockIdx.x == 0) ? g_w1h : (blockIdx.x == 1) ? g_w2h : g_w3h;
        int outw = (blockIdx.x == 2) ? CC : FH;
        for (int idx = threadIdx.x; idx < outw * FH; idx += blockDim.x) {
            int n = idx >> 6, k = idx & 63;
            dst[idx] = __float2half(Ws[k * outw + n]);   // Wt[n][k] = W[k][n]
        }
    }
}

// ---------------- degree histogram (4 edges/thread, int4 loads) --------------
__global__ void hist_kernel(const int4* __restrict__ row4, const int4* __restrict__ col4) {
    int q = blockIdx.x * blockDim.x + threadIdx.x;
    if (q >= EE / 4) return;
    int4 r = row4[q];
    int4 c = col4[q];
    atomicAdd(&g_deg_out[r.x], 1); atomicAdd(&g_deg_out[r.y], 1);
    atomicAdd(&g_deg_out[r.z], 1); atomicAdd(&g_deg_out[r.w], 1);
    atomicAdd(&g_deg_in[c.x], 1);  atomicAdd(&g_deg_in[c.y], 1);
    atomicAdd(&g_deg_in[c.z], 1);  atomicAdd(&g_deg_in[c.w], 1);
}

// ---------------- range assignment (warp-aggregated bump alloc) + inv degs --
__global__ void ranges_kernel() {
    int i = blockIdx.x * blockDim.x + threadIdx.x;
    int lane = threadIdx.x & 31;
    int d = (i < NN) ? g_deg_out[i] : 0;
    int incl = d;
#pragma unroll
    for (int o = 1; o < 32; o <<= 1) {
        int v = __shfl_up_sync(0xffffffffu, incl, o);
        if (lane >= o) incl += v;
    }
    int total = __shfl_sync(0xffffffffu, incl, 31);
    unsigned int base = 0;
    if (lane == 31) base = atomicAdd(&g_ctr, (unsigned int)total);
    base = __shfl_sync(0xffffffffu, base, 31);
    if (i < NN) {
        int st = (int)base + (incl - d);
        g_start[i] = st;
        g_pos[i]   = st;
        int di = g_deg_in[i];
        g_invo[i] = (d  > 0) ? rsqrtf((float)d)  : 0.f;
        g_invi[i] = (di > 0) ? rsqrtf((float)di) : 0.f;
    }
}

// ---------------- edge scatter into CSR (4 edges/thread, col only) ----------
__global__ void scatter_kernel(const int4* __restrict__ row4, const int4* __restrict__ col4) {
    int q = blockIdx.x * blockDim.x + threadIdx.x;
    if (q >= EE / 4) return;
    int4 r = row4[q];
    int4 c = col4[q];
    g_csrc[atomicAdd(&g_pos[r.x], 1)] = (unsigned)c.x;
    g_csrc[atomicAdd(&g_pos[r.y], 1)] = (unsigned)c.y;
    g_csrc[atomicAdd(&g_pos[r.z], 1)] = (unsigned)c.z;
    g_csrc[atomicAdd(&g_pos[r.w], 1)] = (unsigned)c.w;
}

// ---------------- tensor-core GEMM ------------------------------------------
// P[N,OUT](fp16) = invi[n] * X[N,64] @ W[64,OUT], via mma.sync m16n8k16.
// One warp per 16-row tile; ALL A-fragments prefetched first (MLP ~16).
__device__ __forceinline__ void mma16816(float c[4], unsigned a0, unsigned a1,
                                         unsigned a2, unsigned a3,
                                         unsigned b0, unsigned b1) {
    asm volatile(
        "mma.sync.aligned.m16n8k16.row.col.f32.f16.f16.f32 "
        "{%0,%1,%2,%3}, {%4,%5,%6,%7}, {%8,%9}, {%0,%1,%2,%3};\n"
        : "+f"(c[0]), "+f"(c[1]), "+f"(c[2]), "+f"(c[3])
        : "r"(a0), "r"(a1), "r"(a2), "r"(a3), "r"(b0), "r"(b1));
}

template <int OUT, int PSTRIDE, bool F32IN>
__global__ void gemm_mma_kernel(const void* __restrict__ Xin,
                                const __half* __restrict__ Wt,
                                __half* __restrict__ P) {
    const int w = threadIdx.x >> 5, lane = threadIdx.x & 31;
    const int tile = blockIdx.x * 4 + w;
    const int row0 = tile * 16;
    if (row0 >= NN) return;
    const int g = lane >> 2, tg = lane & 3;
    const int r1 = row0 + g, r2 = row0 + g + 8;
    constexpr int NT = OUT / 8;

    // ---- prefetch all A fragments (16 independent loads) ----
    unsigned au[4][4];
    if (F32IN) {
        const float* X = (const float*)Xin;
        float2 f[4][4];
#pragma unroll
        for (int ks = 0; ks < 4; ks++) {
            const int k0 = ks * 16 + tg * 2;
            f[ks][0] = *(const float2*)(X + (size_t)r1 * FH + k0);
            f[ks][1] = *(const float2*)(X + (size_t)r2 * FH + k0);
            f[ks][2] = *(const float2*)(X + (size_t)r1 * FH + k0 + 8);
            f[ks][3] = *(const float2*)(X + (size_t)r2 * FH + k0 + 8);
        }
#pragma unroll
        for (int ks = 0; ks < 4; ks++) {
#pragma unroll
            for (int j = 0; j < 4; j++) {
                __half2 h = __floats2half2_rn(f[ks][j].x, f[ks][j].y);
                au[ks][j] = *(unsigned*)&h;
            }
        }
    } else {
        const __half* Xh = (const __half*)Xin;
#pragma unroll
        for (int ks = 0; ks < 4; ks++) {
            const int k0 = ks * 16 + tg * 2;
            au[ks][0] = *(const unsigned*)(Xh + (size_t)r1 * FH + k0);
            au[ks][1] = *(const unsigned*)(Xh + (size_t)r2 * FH + k0);
            au[ks][2] = *(const unsigned*)(Xh + (size_t)r1 * FH + k0 + 8);
            au[ks][3] = *(const unsigned*)(Xh + (size_t)r2 * FH + k0 + 8);
        }
    }

    float acc[NT][4];
#pragma unroll
    for (int nt = 0; nt < NT; nt++) {
        acc[nt][0] = 0.f; acc[nt][1] = 0.f; acc[nt][2] = 0.f; acc[nt][3] = 0.f;
    }

#pragma unroll
    for (int ks = 0; ks < 4; ks++) {
        const int k0 = ks * 16 + tg * 2;
#pragma unroll
        for (int nt = 0; nt < NT; nt++) {
            unsigned b0 = *(const unsigned*)(Wt + (nt * 8 + g) * FH + k0);
            unsigned b1 = *(const unsigned*)(Wt + (nt * 8 + g) * FH + k0 + 8);
            mma16816(acc[nt], au[ks][0], au[ks][1], au[ks][2], au[ks][3], b0, b1);
        }
    }

    const float inv1 = g_invi[r1], inv2 = g_invi[r2];
#pragma unroll
    for (int nt = 0; nt < NT; nt++) {
        __half2 h1 = __floats2half2_rn(acc[nt][0] * inv1, acc[nt][1] * inv1);
        __half2 h2 = __floats2half2_rn(acc[nt][2] * inv2, acc[nt][3] * inv2);
        *(__half2*)(P + (size_t)r1 * PSTRIDE + nt * 8 + tg * 2) = h1;
        *(__half2*)(P + (size_t)r2 * PSTRIDE + nt * 8 + tg * 2) = h2;
    }
}

// ---------------- half-warp gather SpMM, width 64 ----------------------------
__device__ __forceinline__ void acc4(float& a0, float& a1, float& a2, float& a3,
                                     uint2 v) {
    __half2 h0 = *reinterpret_cast<__half2*>(&v.x);
    __half2 h1 = *reinterpret_cast<__half2*>(&v.y);
    float2 f0 = __half22float2(h0);
    float2 f1 = __half22float2(h1);
    a0 += f0.x; a1 += f0.y; a2 += f1.x; a3 += f1.y;
}

// WRITE32: also write fp32 result to Y (layer 2 -> d_out h). Always writes
// fp16 relu'd copy to g_xh (input of next GEMM).
template <bool WRITE32>
__global__ void spmm64_kernel(const uint2* __restrict__ P,   // rows of 16 uint2
                              const float* __restrict__ bias,
                              float* __restrict__ Y) {
    int n = (blockIdx.x * blockDim.x + threadIdx.x) >> 5;
    int lane = threadIdx.x & 31;
    if (n >= NN) return;
    int s = g_start[n];
    int d = g_deg_out[n];
    const int half = lane >> 4;
    const int l16  = lane & 15;
    const unsigned* cs = g_csrc + s;
    float a0 = 0.f, a1 = 0.f, a2 = 0.f, a3 = 0.f;
    int e = 0;
    for (; e + 16 <= d; e += 16) {              // 16 edges: 8 gathers in flight
        unsigned c[8];
#pragma unroll
        for (int i = 0; i < 8; i++) c[i] = cs[e + 2 * i + half];
        uint2 v[8];
#pragma unroll
        for (int i = 0; i < 8; i++) v[i] = __ldg(P + c[i] * 16u + l16);
#pragma unroll
        for (int i = 0; i < 8; i++) acc4(a0, a1, a2, a3, v[i]);
    }
    if (e + 8 <= d) {
        unsigned c[4];
#pragma unroll
        for (int i = 0; i < 4; i++) c[i] = cs[e + 2 * i + half];
        uint2 v[4];
#pragma unroll
        for (int i = 0; i < 4; i++) v[i] = __ldg(P + c[i] * 16u + l16);
#pragma unroll
        for (int i = 0; i < 4; i++) acc4(a0, a1, a2, a3, v[i]);
        e += 8;
    }
    for (; e + 2 <= d; e += 2) {
        unsigned c = cs[e + half];
        uint2 v = __ldg(P + c * 16u + l16);
        acc4(a0, a1, a2, a3, v);
    }
    if (e < d && half == 0) {
        unsigned c = cs[e];
        uint2 v = __ldg(P + c * 16u + l16);
        acc4(a0, a1, a2, a3, v);
    }
    a0 += __shfl_xor_sync(0xffffffffu, a0, 16);
    a1 += __shfl_xor_sync(0xffffffffu, a1, 16);
    a2 += __shfl_xor_sync(0xffffffffu, a2, 16);
    a3 += __shfl_xor_sync(0xffffffffu, a3, 16);
    if (half == 0) {
        float inv = g_invo[n];
        const float4 bb = *reinterpret_cast<const float4*>(bias + 4 * l16);
        float r0 = fmaf(inv, a0, bb.x);
        float r1 = fmaf(inv, a1, bb.y);
        float r2 = fmaf(inv, a2, bb.z);
        float r3 = fmaf(inv, a3, bb.w);
        if (WRITE32) {
            *reinterpret_cast<float4*>(Y + (size_t)n * FH + 4 * l16) =
                make_float4(r0, r1, r2, r3);
        }
        __half2 q0 = __floats2half2_rn(fmaxf(r0, 0.f), fmaxf(r1, 0.f));
        __half2 q1 = __floats2half2_rn(fmaxf(r2, 0.f), fmaxf(r3, 0.f));
        uint2 q = make_uint2(*(unsigned*)&q0, *(unsigned*)&q1);
        *reinterpret_cast<uint2*>(g_xh + (size_t)n * FH + 4 * l16) = q;
    }
}

// ---------------- gather SpMM width 40 (padded fp16 rows) + log-softmax ------
__global__ void spmm40_lsm_kernel(const __half2* __restrict__ P,
                                  const float* __restrict__ bias,
                                  float* __restrict__ O) {
    int n = (blockIdx.x * blockDim.x + threadIdx.x) >> 5;
    int lane = threadIdx.x & 31;
    if (n >= NN) return;
    int s = g_start[n];
    int d = g_deg_out[n];
    const bool act = (lane < CC / 2);   // lanes 0..19 own feature pairs
    float a0 = 0.f, a1 = 0.f, b0 = 0.f, b1 = 0.f;
    const unsigned* cs = g_csrc + s;
    int e = 0;
    for (; e + 8 <= d; e += 8) {                // 8 gathers in flight
        unsigned c[8];
#pragma unroll
        for (int i = 0; i < 8; i++) c[i] = cs[e + i];
        if (act) {
            float2 v[8];
#pragma unroll
            for (int i = 0; i < 8; i++)
                v[i] = __half22float2(__ldg(P + c[i] * (unsigned)(P3S / 2) + lane));
#pragma unroll
            for (int i = 0; i < 8; i += 2) {
                a0 += v[i].x;     a1 += v[i].y;
                b0 += v[i + 1].x; b1 += v[i + 1].y;
            }
        }
    }
    for (; e < d; e++) {
        unsigned c0 = cs[e];
        if (act) {
            float2 v0 = __half22float2(__ldg(P + c0 * (unsigned)(P3S / 2) + lane));
            a0 += v0.x; a1 += v0.y;
        }
    }
    a0 += b0; a1 += b1;
    float inv = g_invo[n];
    float t0 = act ? fmaf(inv, a0, bias[2 * lane])     : 0.f;
    float t1 = act ? fmaf(inv, a1, bias[2 * lane + 1]) : 0.f;
    float m = act ? fmaxf(t0, t1) : -INFINITY;
#pragma unroll
    for (int o = 16; o; o >>= 1) m = fmaxf(m, __shfl_xor_sync(0xffffffffu, m, o));
    float sum = act ? (expf(t0 - m) + expf(t1 - m)) : 0.f;
#pragma unroll
    for (int o = 16; o; o >>= 1) sum += __shfl_xor_sync(0xffffffffu, sum, o);
    float ls = m + logf(sum);
    if (act) {
        *reinterpret_cast<float2*>(O + (size_t)n * CC + 2 * lane) =
            make_float2(t0 - ls, t1 - ls);
    }
}

// ---------------- launch -----------------------------------------------------
extern "C" void kernel_launch(void* const* d_in, const int* in_sizes, int n_in,
                              void* d_out, int out_size) {
    const float* x   = (const float*)d_in[0];
    const int*   ei  = (const int*)d_in[1];
    const int4*  row4 = (const int4*)ei;
    const int4*  col4 = (const int4*)(ei + EE);
    const float* W1s = (const float*)d_in[2];
    const float* b1s = (const float*)d_in[3];
    const float* W2s = (const float*)d_in[6];
    const float* b2s = (const float*)d_in[7];
    const float* Wos = (const float*)d_in[10];
    const float* bos = (const float*)d_in[11];

    float* out = (float*)d_out;
    float* h   = out;                       // [N, 64]
    float* lsm = out + (size_t)NN * FH;     // [N, 40]

    __half *pp, *pxh, *pw1, *pw2, *pw3;
    cudaGetSymbolAddress((void**)&pp,  g_p);
    cudaGetSymbolAddress((void**)&pxh, g_xh);
    cudaGetSymbolAddress((void**)&pw1, g_w1h);
    cudaGetSymbolAddress((void**)&pw2, g_w2h);
    cudaGetSymbolAddress((void**)&pw3, g_w3h);

    const int T = 256;
    const int WARPS_GRID = (NN * 32 + T - 1) / T;
    const int Q = EE / 4;
    const int GEMM_GRID = (NN / 16 + 3) / 4;   // 4 warp-tiles of 16 rows per block

    // ---- CSR build + weight conversion; gemm1 in profile slot 4 ----
    zero_kernel<<<(NN + T - 1) / T, T>>>(W1s, W2s, Wos);
    hist_kernel<<<(Q + T - 1) / T, T>>>(row4, col4);
    ranges_kernel<<<(NN + T - 1) / T, T>>>();
    gemm_mma_kernel<FH, FH, true><<<GEMM_GRID, 128>>>(x, pw1, pp);
    scatter_kernel<<<(Q + T - 1) / T, T>>>(row4, col4);

    // ---- layer 1 aggregate (writes fp16 relu to g_xh only) ----
    spmm64_kernel<false><<<WARPS_GRID, T>>>((const uint2*)pp, b1s, h);
    // ---- layer 2 ----
    gemm_mma_kernel<FH, FH, false><<<GEMM_GRID, 128>>>(pxh, pw2, pp);
    spmm64_kernel<true><<<WARPS_GRID, T>>>((const uint2*)pp, b2s, h);
    // ---- layer 3 ----
    gemm_mma_kernel<CC, P3S, false><<<GEMM_GRID, 128>>>(pxh, pw3, pp);
    spmm40_lsm_kernel<<<WARPS_GRID, T>>>((const __half2*)pp, bos, lsm);
}

// round 9
// speedup vs baseline: 1.9960x; 1.1922x over previous
#include <cuda_runtime.h>
#include <cuda_fp16.h>
#include <math.h>

#define NN 100000
#define EE 1600000
#define FH 64      // input/hidden width
#define CC 40      // output classes
#define P3S 48     // padded layer-3 P row stride in halves (96 B = 3 sectors)

// ---------------- scratch (device globals; no allocation allowed) ----------
__device__ int   g_deg_out[NN];
__device__ int   g_deg_in[NN];
__device__ float g_invo[NN];
__device__ float g_invi[NN];
__device__ int   g_start[NN];              // CSR row start
__device__ int   g_pos[NN];                // bump cursor per row
__device__ unsigned g_csrc[EE];            // CSR col only (weights folded out)
__device__ unsigned int g_ctr;             // global bump counter
__device__ __half g_p[(size_t)NN * FH];    // fp16 GEMM output (invi-scaled)
__device__ __half g_xh[(size_t)NN * FH];   // fp16 relu'd SpMM output (next GEMM in)
__device__ uint2  g_wf1[8 * 4 * 32];       // W1 fragment-major: [nt][ks][lane]
__device__ uint2  g_wf2[8 * 4 * 32];       // W2 fragment-major
__device__ uint2  g_wf3[5 * 4 * 32];       // Wo fragment-major (NT=5)

// ---------------- helpers ----------------------------------------------------
__device__ __forceinline__ unsigned smem_u32(const void* p) {
    return (unsigned)__cvta_generic_to_shared(p);
}
__device__ __forceinline__ void ldmatrix_x4(unsigned& a0, unsigned& a1,
                                            unsigned& a2, unsigned& a3,
                                            unsigned addr) {
    asm volatile("ldmatrix.sync.aligned.m8n8.x4.shared.b16 {%0,%1,%2,%3}, [%4];"
                 : "=r"(a0), "=r"(a1), "=r"(a2), "=r"(a3) : "r"(addr));
}
__device__ __forceinline__ void mma16816(float c[4], unsigned a0, unsigned a1,
                                         unsigned a2, unsigned a3,
                                         unsigned b0, unsigned b1) {
    asm volatile(
        "mma.sync.aligned.m16n8k16.row.col.f32.f16.f16.f32 "
        "{%0,%1,%2,%3}, {%4,%5,%6,%7}, {%8,%9}, {%0,%1,%2,%3};\n"
        : "+f"(c[0]), "+f"(c[1]), "+f"(c[2]), "+f"(c[3])
        : "r"(a0), "r"(a1), "r"(a2), "r"(a3), "r"(b0), "r"(b1));
}

// ---------------- zero + weight-fragment precompute ---------------------------
// Fragment layout for mma m16n8k16 B (col): lane(g=l>>2,tg=l&3), frag (nt,ks):
//   b0 = { W[k0][n], W[k0+1][n] },  b1 = { W[k0+8][n], W[k0+9][n] }
//   with n = nt*8+g, k0 = ks*16+tg*2.
__global__ void zero_kernel(const float* __restrict__ W1,
                            const float* __restrict__ W2,
                            const float* __restrict__ W3) {
    int i = blockIdx.x * blockDim.x + threadIdx.x;
    if (i < NN) { g_deg_out[i] = 0; g_deg_in[i] = 0; }
    if (i == 0) g_ctr = 0u;
    if (blockIdx.x < 3) {
        const float* Ws = (blockIdx.x == 0) ? W1 : (blockIdx.x == 1) ? W2 : W3;
        uint2* dst = (blockIdx.x == 0) ? g_wf1 : (blockIdx.x == 1) ? g_wf2 : g_wf3;
        int outw = (blockIdx.x == 2) ? CC : FH;
        int nfr = (outw / 8) * 4 * 32;
        for (int idx = threadIdx.x; idx < nfr; idx += blockDim.x) {
            int lane = idx & 31;
            int ksnt = idx >> 5;
            int ks = ksnt & 3, nt = ksnt >> 2;
            int g = lane >> 2, tg = lane & 3;
            int n = nt * 8 + g;
            int k0 = ks * 16 + tg * 2;
            __half2 lo = __floats2half2_rn(Ws[k0 * outw + n], Ws[(k0 + 1) * outw + n]);
            __half2 hi = __floats2half2_rn(Ws[(k0 + 8) * outw + n], Ws[(k0 + 9) * outw + n]);
            uint2 v;
            v.x = *(unsigned*)&lo;
            v.y = *(unsigned*)&hi;
            dst[idx] = v;
        }
    }
}

// ---------------- degree histogram (4 edges/thread, int4 loads) --------------
__global__ void hist_kernel(const int4* __restrict__ row4, const int4* __restrict__ col4) {
    int q = blockIdx.x * blockDim.x + threadIdx.x;
    if (q >= EE / 4) return;
    int4 r = row4[q];
    int4 c = col4[q];
    atomicAdd(&g_deg_out[r.x], 1); atomicAdd(&g_deg_out[r.y], 1);
    atomicAdd(&g_deg_out[r.z], 1); atomicAdd(&g_deg_out[r.w], 1);
    atomicAdd(&g_deg_in[c.x], 1);  atomicAdd(&g_deg_in[c.y], 1);
    atomicAdd(&g_deg_in[c.z], 1);  atomicAdd(&g_deg_in[c.w], 1);
}

// ---------------- range assignment (warp-aggregated bump alloc) + inv degs --
__global__ void ranges_kernel() {
    int i = blockIdx.x * blockDim.x + threadIdx.x;
    int lane = threadIdx.x & 31;
    int d = (i < NN) ? g_deg_out[i] : 0;
    int incl = d;
#pragma unroll
    for (int o = 1; o < 32; o <<= 1) {
        int v = __shfl_up_sync(0xffffffffu, incl, o);
        if (lane >= o) incl += v;
    }
    int total = __shfl_sync(0xffffffffu, incl, 31);
    unsigned int base = 0;
    if (lane == 31) base = atomicAdd(&g_ctr, (unsigned int)total);
    base = __shfl_sync(0xffffffffu, base, 31);
    if (i < NN) {
        int st = (int)base + (incl - d);
        g_start[i] = st;
        g_pos[i]   = st;
        int di = g_deg_in[i];
        g_invo[i] = (d  > 0) ? rsqrtf((float)d)  : 0.f;
        g_invi[i] = (di > 0) ? rsqrtf((float)di) : 0.f;
    }
}

// ---------------- edge scatter into CSR (4 edges/thread, col only) ----------
__global__ void scatter_kernel(const int4* __restrict__ row4, const int4* __restrict__ col4) {
    int q = blockIdx.x * blockDim.x + threadIdx.x;
    if (q >= EE / 4) return;
    int4 r = row4[q];
    int4 c = col4[q];
    g_csrc[atomicAdd(&g_pos[r.x], 1)] = (unsigned)c.x;
    g_csrc[atomicAdd(&g_pos[r.y], 1)] = (unsigned)c.y;
    g_csrc[atomicAdd(&g_pos[r.z], 1)] = (unsigned)c.z;
    g_csrc[atomicAdd(&g_pos[r.w], 1)] = (unsigned)c.w;
}

// ---------------- tensor-core GEMM (smem staged + ldmatrix) -------------------
// P[N,OUT](fp16) = invi[n] * X[N,64] @ W.  256 threads = 8 warps; 128 rows/block.
// smem tile: 128 rows x 64 halves, 16B-chunk swizzle: chunk ^= (row & 7).
template <int OUT, int PSTRIDE, bool F32IN>
__global__ __launch_bounds__(256) void gemm_mma_kernel(
        const void* __restrict__ Xin,
        const uint2* __restrict__ Wf,
        __half* __restrict__ P) {
    __shared__ __align__(16) char sA[128 * 128];   // 16KB, reused for epilogue
    const int tid = threadIdx.x;
    const int w = tid >> 5, lane = tid & 31;
    const int row0 = blockIdx.x * 128;
    constexpr int NT = OUT / 8;

    // ---- stage X tile into swizzled smem (coalesced LDG.128) ----
    if (F32IN) {
        const float4* X4 = (const float4*)Xin;   // row = 16 float4
#pragma unroll
        for (int i = 0; i < 8; i++) {
            int idx = tid + i * 256;              // float4 index in tile
            int row = idx >> 4, j = idx & 15;     // j: float4 within row
            int grow = row0 + row;
            float4 v = make_float4(0.f, 0.f, 0.f, 0.f);
            if (grow < NN) v = X4[(size_t)grow * 16 + j];
            __half2 h0 = __floats2half2_rn(v.x, v.y);
            __half2 h1 = __floats2half2_rn(v.z, v.w);
            int chunk = j >> 1, sub = (j & 1) * 8;
            uint2* dst = (uint2*)(sA + row * 128 + ((chunk ^ (row & 7)) << 4) + sub);
            *dst = make_uint2(*(unsigned*)&h0, *(unsigned*)&h1);
        }
    } else {
        const uint4* X4 = (const uint4*)Xin;     // row = 8 uint4
#pragma unroll
        for (int i = 0; i < 4; i++) {
            int idx = tid + i * 256;
            int row = idx >> 3, chunk = idx & 7;
            int grow = row0 + row;
            uint4 v = make_uint4(0u, 0u, 0u, 0u);
            if (grow < NN) v = X4[(size_t)grow * 8 + chunk];
            *(uint4*)(sA + row * 128 + ((chunk ^ (row & 7)) << 4)) = v;
        }
    }
    __syncthreads();

    // ---- A fragments via ldmatrix.x4 (4 per warp) ----
    const int lrow0 = w * 16;
    unsigned a[4][4];
#pragma unroll
    for (int ks = 0; ks < 4; ks++) {
        int lr = lrow0 + (lane & 15);
        int chunk = ks * 2 + (lane >> 4);
        unsigned addr = smem_u32(sA + lr * 128 + ((chunk ^ (lr & 7)) << 4));
        ldmatrix_x4(a[ks][0], a[ks][1], a[ks][2], a[ks][3], addr);
    }

    float acc[NT][4];
#pragma unroll
    for (int nt = 0; nt < NT; nt++) {
        acc[nt][0] = 0.f; acc[nt][1] = 0.f; acc[nt][2] = 0.f; acc[nt][3] = 0.f;
    }
#pragma unroll
    for (int ks = 0; ks < 4; ks++) {
#pragma unroll
        for (int nt = 0; nt < NT; nt++) {
            uint2 b = __ldg(Wf + (nt * 4 + ks) * 32 + lane);
            mma16816(acc[nt], a[ks][0], a[ks][1], a[ks][2], a[ks][3], b.x, b.y);
        }
    }

    // ---- epilogue: scale, write frags to swizzled smem, coalesced STG ----
    const int g = lane >> 2, tg = lane & 3;
    const int rl1 = lrow0 + g, rl2 = lrow0 + g + 8;
    const int gr1 = row0 + rl1, gr2 = row0 + rl2;
    const float inv1 = (gr1 < NN) ? g_invi[gr1] : 0.f;
    const float inv2 = (gr2 < NN) ? g_invi[gr2] : 0.f;
    __syncthreads();                             // done reading sA as input
#pragma unroll
    for (int nt = 0; nt < NT; nt++) {
        __half2 h1 = __floats2half2_rn(acc[nt][0] * inv1, acc[nt][1] * inv1);
        __half2 h2 = __floats2half2_rn(acc[nt][2] * inv2, acc[nt][3] * inv2);
        *(unsigned*)(sA + rl1 * 128 + ((nt ^ (rl1 & 7)) << 4) + tg * 4) = *(unsigned*)&h1;
        *(unsigned*)(sA + rl2 * 128 + ((nt ^ (rl2 & 7)) << 4) + tg * 4) = *(unsigned*)&h2;
    }
    __syncthreads();

    if (PSTRIDE == 64) {
#pragma unroll
        for (int i = 0; i < 4; i++) {
            int idx = tid + i * 256;
            int row = idx >> 3, chunk = idx & 7;
            int grow = row0 + row;
            if (grow < NN) {
                uint4 v = *(const uint4*)(sA + row * 128 + ((chunk ^ (row & 7)) << 4));
                *(uint4*)((char*)P + (size_t)grow * 128 + chunk * 16) = v;
            }
        }
    } else {  // PSTRIDE = 48 halves = 96B rows (6 chunks; padding bytes are junk)
#pragma unroll
        for (int i = 0; i < 3; i++) {
            int idx = tid + i * 256;              // 768 = 128 rows * 6 chunks
            int row = idx / 6, c = idx % 6;
            int grow = row0 + row;
            if (grow < NN) {
                uint4 v = *(const uint4*)(sA + row * 128 + ((c ^ (row & 7)) << 4));
                *(uint4*)((char*)P + (size_t)grow * 96 + c * 16) = v;
            }
        }
    }
}

// ---------------- half-warp gather SpMM, width 64 ----------------------------
__device__ __forceinline__ void acc4(float& a0, float& a1, float& a2, float& a3,
                                     uint2 v) {
    __half2 h0 = *reinterpret_cast<__half2*>(&v.x);
    __half2 h1 = *reinterpret_cast<__half2*>(&v.y);
    float2 f0 = __half22float2(h0);
    float2 f1 = __half22float2(h1);
    a0 += f0.x; a1 += f0.y; a2 += f1.x; a3 += f1.y;
}

template <bool WRITE32>
__global__ void spmm64_kernel(const uint2* __restrict__ P,   // rows of 16 uint2
                              const float* __restrict__ bias,
                              float* __restrict__ Y) {
    int n = (blockIdx.x * blockDim.x + threadIdx.x) >> 5;
    int lane = threadIdx.x & 31;
    if (n >= NN) return;
    int s = g_start[n];
    int d = g_deg_out[n];
    const int half = lane >> 4;
    const int l16  = lane & 15;
    const unsigned* cs = g_csrc + s;
    float a0 = 0.f, a1 = 0.f, a2 = 0.f, a3 = 0.f;
    int e = 0;
    for (; e + 16 <= d; e += 16) {
        unsigned c[8];
#pragma unroll
        for (int i = 0; i < 8; i++) c[i] = cs[e + 2 * i + half];
        uint2 v[8];
#pragma unroll
        for (int i = 0; i < 8; i++) v[i] = __ldg(P + c[i] * 16u + l16);
#pragma unroll
        for (int i = 0; i < 8; i++) acc4(a0, a1, a2, a3, v[i]);
    }
    if (e + 8 <= d) {
        unsigned c[4];
#pragma unroll
        for (int i = 0; i < 4; i++) c[i] = cs[e + 2 * i + half];
        uint2 v[4];
#pragma unroll
        for (int i = 0; i < 4; i++) v[i] = __ldg(P + c[i] * 16u + l16);
#pragma unroll
        for (int i = 0; i < 4; i++) acc4(a0, a1, a2, a3, v[i]);
        e += 8;
    }
    for (; e + 2 <= d; e += 2) {
        unsigned c = cs[e + half];
        uint2 v = __ldg(P + c * 16u + l16);
        acc4(a0, a1, a2, a3, v);
    }
    if (e < d && half == 0) {
        unsigned c = cs[e];
        uint2 v = __ldg(P + c * 16u + l16);
        acc4(a0, a1, a2, a3, v);
    }
    a0 += __shfl_xor_sync(0xffffffffu, a0, 16);
    a1 += __shfl_xor_sync(0xffffffffu, a1, 16);
    a2 += __shfl_xor_sync(0xffffffffu, a2, 16);
    a3 += __shfl_xor_sync(0xffffffffu, a3, 16);
    if (half == 0) {
        float inv = g_invo[n];
        const float4 bb = *reinterpret_cast<const float4*>(bias + 4 * l16);
        float r0 = fmaf(inv, a0, bb.x);
        float r1 = fmaf(inv, a1, bb.y);
        float r2 = fmaf(inv, a2, bb.z);
        float r3 = fmaf(inv, a3, bb.w);
        if (WRITE32) {
            *reinterpret_cast<float4*>(Y + (size_t)n * FH + 4 * l16) =
                make_float4(r0, r1, r2, r3);
        }
        __half2 q0 = __floats2half2_rn(fmaxf(r0, 0.f), fmaxf(r1, 0.f));
        __half2 q1 = __floats2half2_rn(fmaxf(r2, 0.f), fmaxf(r3, 0.f));
        uint2 q = make_uint2(*(unsigned*)&q0, *(unsigned*)&q1);
        *reinterpret_cast<uint2*>(g_xh + (size_t)n * FH + 4 * l16) = q;
    }
}

// ---------------- gather SpMM width 40 (padded fp16 rows) + log-softmax ------
__global__ void spmm40_lsm_kernel(const __half2* __restrict__ P,
                                  const float* __restrict__ bias,
                                  float* __restrict__ O) {
    int n = (blockIdx.x * blockDim.x + threadIdx.x) >> 5;
    int lane = threadIdx.x & 31;
    if (n >= NN) return;
    int s = g_start[n];
    int d = g_deg_out[n];
    const bool act = (lane < CC / 2);
    float a0 = 0.f, a1 = 0.f, b0 = 0.f, b1 = 0.f;
    const unsigned* cs = g_csrc + s;
    int e = 0;
    for (; e + 8 <= d; e += 8) {
        unsigned c[8];
#pragma unroll
        for (int i = 0; i < 8; i++) c[i] = cs[e + i];
        if (act) {
            float2 v[8];
#pragma unroll
            for (int i = 0; i < 8; i++)
                v[i] = __half22float2(__ldg(P + c[i] * (unsigned)(P3S / 2) + lane));
#pragma unroll
            for (int i = 0; i < 8; i += 2) {
                a0 += v[i].x;     a1 += v[i].y;
                b0 += v[i + 1].x; b1 += v[i + 1].y;
            }
        }
    }
    for (; e < d; e++) {
        unsigned c0 = cs[e];
        if (act) {
            float2 v0 = __half22float2(__ldg(P + c0 * (unsigned)(P3S / 2) + lane));
            a0 += v0.x; a1 += v0.y;
        }
    }
    a0 += b0; a1 += b1;
    float inv = g_invo[n];
    float t0 = act ? fmaf(inv, a0, bias[2 * lane])     : 0.f;
    float t1 = act ? fmaf(inv, a1, bias[2 * lane + 1]) : 0.f;
    float m = act ? fmaxf(t0, t1) : -INFINITY;
#pragma unroll
    for (int o = 16; o; o >>= 1) m = fmaxf(m, __shfl_xor_sync(0xffffffffu, m, o));
    float sum = act ? (expf(t0 - m) + expf(t1 - m)) : 0.f;
#pragma unroll
    for (int o = 16; o; o >>= 1) sum += __shfl_xor_sync(0xffffffffu, sum, o);
    float ls = m + logf(sum);
    if (act) {
        *reinterpret_cast<float2*>(O + (size_t)n * CC + 2 * lane) =
            make_float2(t0 - ls, t1 - ls);
    }
}

// ---------------- launch -----------------------------------------------------
extern "C" void kernel_launch(void* const* d_in, const int* in_sizes, int n_in,
                              void* d_out, int out_size) {
    const float* x   = (const float*)d_in[0];
    const int*   ei  = (const int*)d_in[1];
    const int4*  row4 = (const int4*)ei;
    const int4*  col4 = (const int4*)(ei + EE);
    const float* W1s = (const float*)d_in[2];
    const float* b1s = (const float*)d_in[3];
    const float* W2s = (const float*)d_in[6];
    const float* b2s = (const float*)d_in[7];
    const float* Wos = (const float*)d_in[10];
    const float* bos = (const float*)d_in[11];

    float* out = (float*)d_out;
    float* h   = out;                       // [N, 64]
    float* lsm = out + (size_t)NN * FH;     // [N, 40]

    __half *pp, *pxh;
    uint2 *pw1, *pw2, *pw3;
    cudaGetSymbolAddress((void**)&pp,  g_p);
    cudaGetSymbolAddress((void**)&pxh, g_xh);
    cudaGetSymbolAddress((void**)&pw1, g_wf1);
    cudaGetSymbolAddress((void**)&pw2, g_wf2);
    cudaGetSymbolAddress((void**)&pw3, g_wf3);

    const int T = 256;
    const int WARPS_GRID = (NN * 32 + T - 1) / T;
    const int Q = EE / 4;
    const int GEMM_GRID = (NN + 127) / 128;

    // ---- CSR build + weight conversion; gemm1 in profile slot 4 ----
    zero_kernel<<<(NN + T - 1) / T, T>>>(W1s, W2s, Wos);
    hist_kernel<<<(Q + T - 1) / T, T>>>(row4, col4);
    ranges_kernel<<<(NN + T - 1) / T, T>>>();
    gemm_mma_kernel<FH, FH, true><<<GEMM_GRID, 256>>>(x, pw1, pp);
    scatter_kernel<<<(Q + T - 1) / T, T>>>(row4, col4);

    // ---- layer 1 aggregate (writes fp16 relu to g_xh only) ----
    spmm64_kernel<false><<<WARPS_GRID, T>>>((const uint2*)pp, b1s, h);
    // ---- layer 2 ----
    gemm_mma_kernel<FH, FH, false><<<GEMM_GRID, 256>>>(pxh, pw2, pp);
    spmm64_kernel<true><<<WARPS_GRID, T>>>((const uint2*)pp, b2s, h);
    // ---- layer 3 ----
    gemm_mma_kernel<CC, P3S, false><<<GEMM_GRID, 256>>>(pxh, pw3, pp);
    spmm40_lsm_kernel<<<WARPS_GRID, T>>>((const __half2*)pp, bos, lsm);
}